// round 9
// baseline (speedup 1.0000x reference)
#include <cuda_runtime.h>
#include <cstdint>

// Shapes fixed: B=4, N=4096, D=1024, H=16, d_head=64.
#define BB 4
#define NN 4096
#define DD 1024
#define DW 512            // packed bf16x2 words per row of 1024
#define HH 16
#define DH 64
#define CTXSP 2
#define SCALE 0.5946035575013605f   // (d_head^0.5)^(-0.25) = 2^(-0.75)

// Scratch (__device__ globals; no cudaMalloc allowed).
__device__ float    g_Q  [(size_t)BB * NN * DD];   // Q proj, row-softmaxed (fp32, for col_softmax)
__device__ float    g_ctx[(size_t)CTXSP * BB * HH * DH * DH];
__device__ uint32_t g_xb [(size_t)BB * NN * DW];   // x packed bf16
__device__ uint32_t g_Qb [(size_t)BB * NN * DW];   // softmaxed Q packed bf16
__device__ uint32_t g_Vb [(size_t)BB * NN * DW];   // V proj packed bf16
__device__ uint32_t g_KmB[(size_t)BB * NN * DW];   // column-softmax packed bf16
__device__ uint32_t g_Wqb[(size_t)DD * DW];        // Wq^T packed bf16
__device__ uint32_t g_Wvb[(size_t)DD * DW];        // Wv^T packed bf16
__device__ uint32_t g_Mtb[(size_t)BB * DD * DW];   // Mbig^T packed bf16

// ---------------------------------------------------------------------------
// helpers
// ---------------------------------------------------------------------------
__device__ __forceinline__ uint32_t smem_u32(const void* p) {
    uint32_t a;
    asm("{ .reg .u64 t; cvta.to.shared.u64 t, %1; cvt.u32.u64 %0, t; }" : "=r"(a) : "l"(p));
    return a;
}
__device__ __forceinline__ uint32_t pack2(float lo, float hi) {
    uint32_t r;
    asm("cvt.rn.bf16x2.f32 %0, %1, %2;" : "=r"(r) : "f"(hi), "f"(lo));
    return r;
}
#define CP_ASYNC16(dst, src) \
    asm volatile("cp.async.cg.shared.global [%0], [%1], 16;" :: "r"(dst), "l"(src) : "memory")
#define CP_COMMIT()  asm volatile("cp.async.commit_group;" ::: "memory")
#define CP_WAIT2()   asm volatile("cp.async.wait_group 2;" ::: "memory")

#define LDM_X4(r, a)                                                            \
    asm volatile("ldmatrix.sync.aligned.m8n8.x4.shared.b16 {%0,%1,%2,%3}, [%4];"\
        : "=r"((r)[0]), "=r"((r)[1]), "=r"((r)[2]), "=r"((r)[3]) : "r"(a))
#define LDM_X4T(r, a)                                                           \
    asm volatile("ldmatrix.sync.aligned.m8n8.x4.trans.shared.b16 {%0,%1,%2,%3}, [%4];"\
        : "=r"((r)[0]), "=r"((r)[1]), "=r"((r)[2]), "=r"((r)[3]) : "r"(a))
#define MMA_BF16(d, a, b0, b1)                                                  \
    asm volatile("mma.sync.aligned.m16n8k16.row.col.f32.bf16.bf16.f32 "         \
        "{%0,%1,%2,%3}, {%4,%5,%6,%7}, {%8,%9}, {%0,%1,%2,%3};"                 \
        : "+f"((d)[0]), "+f"((d)[1]), "+f"((d)[2]), "+f"((d)[3])                \
        : "r"((a)[0]), "r"((a)[1]), "r"((a)[2]), "r"((a)[3]), "r"(b0), "r"(b1))

// ---------------------------------------------------------------------------
// bf16 mma.sync GEMM.  MODE 0: C=fp32+bias.  MODE 1: row-softmax(+bias) over
// 64-col heads (warp-internal!), fp32 C AND packed Cb.  MODE 2: packed only.
// CTA 256x128, 8 warps as 4(m) x 2(n), warp tile 64x64 (LDSM:HMMA = 1:4).
// K-chunk 32 bf16, 4-stage cp.async ring (24KB/stage), 1 CTA/SM.
// ---------------------------------------------------------------------------
#define GEMM_SMEM 98304
#define STG_B 24576

template <int MODE>
__global__ void __launch_bounds__(256)
gemm_bf16(const uint32_t* __restrict__ A, const uint32_t* __restrict__ Bt,
          const float* __restrict__ bias, float* __restrict__ C,
          uint32_t* __restrict__ Cb,
          long long sA, long long sB, long long sC)
{
    extern __shared__ uint32_t sm[];

    const int b = blockIdx.z;
    A  += (long long)b * sA;
    Bt += (long long)b * sB;
    C  += (long long)b * sC;
    Cb += (long long)b * NN * DW;
    const int n0 = blockIdx.x << 7;   // 128-wide n tile
    const int m0 = blockIdx.y << 8;   // 256-wide m tile
    const int tid = threadIdx.x, lane = tid & 31, wid = tid >> 5;
    const int wm = wid >> 1, wn = wid & 1;

    const uint32_t sbase = smem_u32(sm);

    // ---- A loader: one full 64B row per thread (4 x 16B chunks) ------------
    const uint32_t* Ap = A + (long long)(m0 + tid) * DW;
    const int swA = (tid >> 1) & 3;
    uint32_t stA[4];
    #pragma unroll
    for (int j = 0; j < 4; j++)
        stA[j] = sbase + (tid << 6) + (uint32_t)((j ^ swA) << 4);
    // ---- B loader: 2 threads per row, 2 chunks each ------------------------
    const int lrB = tid >> 1, lkB2 = (tid & 1) << 1;
    const uint32_t* Bp = Bt + (long long)(n0 + lrB) * DW + ((tid & 1) << 3);
    const int swB = (lrB >> 1) & 3;
    const uint32_t stB0 = sbase + 16384u + (lrB << 6) + (uint32_t)((lkB2 ^ swB) << 4);
    const uint32_t stB1 = sbase + 16384u + (lrB << 6) + (uint32_t)(((lkB2 + 1) ^ swB) << 4);

    auto issue = [&](int t) {
        const uint32_t so = (uint32_t)(t & 3) * STG_B;
        const uint32_t* a  = Ap + (t << 4);
        const uint32_t* bb = Bp + (t << 4);
        CP_ASYNC16(stA[0] + so, a);
        CP_ASYNC16(stA[1] + so, a + 4);
        CP_ASYNC16(stA[2] + so, a + 8);
        CP_ASYNC16(stA[3] + so, a + 12);
        CP_ASYNC16(stB0 + so, bb);
        CP_ASYNC16(stB1 + so, bb + 4);
    };

    const int ar16 = lane & 15;
    const int acs  = lane >> 4;
    const int aswz = (ar16 >> 1) & 3;
    const int br16 = (lane & 7) | ((lane & 16) >> 1);
    const int bcs  = (lane >> 3) & 1;
    const int bswz = (br16 >> 1) & 3;

    float acc[4][8][4];
    #pragma unroll
    for (int i = 0; i < 4; i++)
        #pragma unroll
        for (int j = 0; j < 8; j++)
            #pragma unroll
            for (int r = 0; r < 4; r++) acc[i][j][r] = 0.f;

    auto compute = [&](int stg) {
        const uint32_t so = (uint32_t)stg * STG_B;
        const uint32_t abase = sbase + so + (((wm << 6) + ar16) << 6);
        const uint32_t bbase = sbase + so + 16384u + (((wn << 6) + br16) << 6);
        #pragma unroll
        for (int ks = 0; ks < 2; ks++) {
            uint32_t af[4][4], bg[4][4];
            const uint32_t ac = (uint32_t)((((ks << 1) + acs) ^ aswz) << 4);
            const uint32_t bc = (uint32_t)((((ks << 1) + bcs) ^ bswz) << 4);
            #pragma unroll
            for (int mf = 0; mf < 4; mf++)
                LDM_X4(af[mf], abase + (uint32_t)(mf << 10) + ac);
            #pragma unroll
            for (int np = 0; np < 4; np++)
                LDM_X4(bg[np], bbase + (uint32_t)(np << 10) + bc);
            #pragma unroll
            for (int mf = 0; mf < 4; mf++)
                #pragma unroll
                for (int nf = 0; nf < 8; nf++)
                    MMA_BF16(acc[mf][nf], af[mf],
                             bg[nf >> 1][(nf & 1) << 1], bg[nf >> 1][((nf & 1) << 1) + 1]);
        }
    };

    issue(0); CP_COMMIT();
    issue(1); CP_COMMIT();
    issue(2); CP_COMMIT();
    for (int t = 0; t < 32; t++) {
        CP_WAIT2();
        __syncthreads();
        compute(t & 3);
        if (t + 3 < 32) issue(t + 3);
        CP_COMMIT();
    }

    // ---- epilogue ----------------------------------------------------------
    const int cbase = n0 + (wn << 6);     // this warp's 64 cols = one head
    float2 bv[8];
    #pragma unroll
    for (int nf = 0; nf < 8; nf++)
        bv[nf] = *(const float2*)(bias + cbase + (nf << 3) + ((lane & 3) << 1));
    #pragma unroll
    for (int mf = 0; mf < 4; mf++)
        #pragma unroll
        for (int nf = 0; nf < 8; nf++) {
            acc[mf][nf][0] += bv[nf].x; acc[mf][nf][1] += bv[nf].y;
            acc[mf][nf][2] += bv[nf].x; acc[mf][nf][3] += bv[nf].y;
        }

    if (MODE == 1) {
        // row softmax over this warp's 64-col head; warp-internal (quad shfl).
        #pragma unroll
        for (int mf = 0; mf < 4; mf++)
            #pragma unroll
            for (int half = 0; half < 2; half++) {
                float mx = acc[mf][0][half * 2];
                #pragma unroll
                for (int nf = 0; nf < 8; nf++) {
                    mx = fmaxf(mx, acc[mf][nf][half * 2]);
                    mx = fmaxf(mx, acc[mf][nf][half * 2 + 1]);
                }
                mx = fmaxf(mx, __shfl_xor_sync(0xffffffffu, mx, 1));
                mx = fmaxf(mx, __shfl_xor_sync(0xffffffffu, mx, 2));
                float s = 0.f;
                #pragma unroll
                for (int nf = 0; nf < 8; nf++) {
                    acc[mf][nf][half * 2]     = __expf(acc[mf][nf][half * 2]     - mx);
                    acc[mf][nf][half * 2 + 1] = __expf(acc[mf][nf][half * 2 + 1] - mx);
                    s += acc[mf][nf][half * 2] + acc[mf][nf][half * 2 + 1];
                }
                s += __shfl_xor_sync(0xffffffffu, s, 1);
                s += __shfl_xor_sync(0xffffffffu, s, 2);
                const float inv = SCALE / s;
                #pragma unroll
                for (int nf = 0; nf < 8; nf++) {
                    acc[mf][nf][half * 2]     *= inv;
                    acc[mf][nf][half * 2 + 1] *= inv;
                }
            }
    }

    #pragma unroll
    for (int mf = 0; mf < 4; mf++) {
        const int r0 = m0 + (wm << 6) + (mf << 4) + (lane >> 2);
        #pragma unroll
        for (int nf = 0; nf < 8; nf++) {
            const int co = (nf << 3) + ((lane & 3) << 1);
            if (MODE != 2) {
                float* Cp = C + (long long)r0 * DD + cbase + co;
                *(float2*)Cp             = make_float2(acc[mf][nf][0], acc[mf][nf][1]);
                *(float2*)(Cp + 8LL*DD)  = make_float2(acc[mf][nf][2], acc[mf][nf][3]);
            }
            if (MODE != 0) {
                const int w = (cbase >> 1) + (nf << 2) + (lane & 3);
                Cb[(size_t)r0 * DW + w]       = pack2(acc[mf][nf][0], acc[mf][nf][1]);
                Cb[(size_t)(r0 + 8) * DW + w] = pack2(acc[mf][nf][2], acc[mf][nf][3]);
            }
        }
    }
}

// ---------------------------------------------------------------------------
// pack_w: W[k][n] -> Wtb[n][k/2] packed bf16 (transpose + pack)
// ---------------------------------------------------------------------------
__global__ void __launch_bounds__(256) pack_w(const float* __restrict__ W,
                                              uint32_t* __restrict__ Wtb)
{
    __shared__ float s[64][36];
    const int n0 = blockIdx.x << 5, k0 = blockIdx.y << 6;
    const int tid = threadIdx.x;
    {
        const int i = tid >> 2, j8 = (tid & 3) << 3;
        *(float4*)&s[i][j8]     = *(const float4*)(W + (size_t)(k0 + i) * DD + n0 + j8);
        *(float4*)&s[i][j8 + 4] = *(const float4*)(W + (size_t)(k0 + i) * DD + n0 + j8 + 4);
    }
    __syncthreads();
    const int nl = tid >> 3, kg = tid & 7;
    uint4 o;
    o.x = pack2(s[kg * 8 + 0][nl], s[kg * 8 + 1][nl]);
    o.y = pack2(s[kg * 8 + 2][nl], s[kg * 8 + 3][nl]);
    o.z = pack2(s[kg * 8 + 4][nl], s[kg * 8 + 5][nl]);
    o.w = pack2(s[kg * 8 + 6][nl], s[kg * 8 + 7][nl]);
    *(uint4*)(Wtb + (size_t)(n0 + nl) * DW + (k0 >> 1) + (kg << 2)) = o;
}

// ---------------------------------------------------------------------------
// pack_rows: fp32 row-major -> packed bf16
// ---------------------------------------------------------------------------
__global__ void __launch_bounds__(256) pack_rows(const float* __restrict__ src,
                                                 uint32_t* __restrict__ dst)
{
    const size_t q = ((size_t)blockIdx.x * 256 + threadIdx.x) << 3;
    float4 a = *(const float4*)(src + q), b = *(const float4*)(src + q + 4);
    uint4 o = {pack2(a.x, a.y), pack2(a.z, a.w), pack2(b.x, b.y), pack2(b.z, b.w)};
    *(uint4*)(dst + (q >> 1)) = o;
}

// ---------------------------------------------------------------------------
// Column softmax over seq dim N -> packed bf16 g_KmB.  32 cols/CTA.
// ---------------------------------------------------------------------------
__global__ void __launch_bounds__(512) col_softmax()
{
    const int b  = blockIdx.y;
    const int c0 = blockIdx.x << 5;
    const int tx = threadIdx.x & 7;
    const int ty = threadIdx.x >> 3;
    const float* src = g_Q + (size_t)b * NN * DD + c0 + (tx << 2);
    uint32_t*    dst = g_KmB + (size_t)b * NN * DW + (c0 >> 1) + (tx << 1);

    __shared__ float4 red[64][8];

    float4 m4 = {-1e30f, -1e30f, -1e30f, -1e30f};
    for (int n = ty; n < NN; n += 64) {
        float4 v = *(const float4*)(src + (size_t)n * DD);
        m4.x = fmaxf(m4.x, v.x); m4.y = fmaxf(m4.y, v.y);
        m4.z = fmaxf(m4.z, v.z); m4.w = fmaxf(m4.w, v.w);
    }
    red[ty][tx] = m4;
    __syncthreads();
    m4 = red[0][tx];
    #pragma unroll 8
    for (int i = 1; i < 64; i++) {
        float4 r = red[i][tx];
        m4.x = fmaxf(m4.x, r.x); m4.y = fmaxf(m4.y, r.y);
        m4.z = fmaxf(m4.z, r.z); m4.w = fmaxf(m4.w, r.w);
    }
    __syncthreads();

    float4 s4 = {0.f, 0.f, 0.f, 0.f};
    for (int n = ty; n < NN; n += 64) {
        float4 v = *(const float4*)(src + (size_t)n * DD);
        s4.x += __expf(v.x - m4.x); s4.y += __expf(v.y - m4.y);
        s4.z += __expf(v.z - m4.z); s4.w += __expf(v.w - m4.w);
    }
    red[ty][tx] = s4;
    __syncthreads();
    s4.x = 0.f; s4.y = 0.f; s4.z = 0.f; s4.w = 0.f;
    #pragma unroll 8
    for (int i = 0; i < 64; i++) {
        float4 r = red[i][tx];
        s4.x += r.x; s4.y += r.y; s4.z += r.z; s4.w += r.w;
    }
    const float4 inv = {SCALE / s4.x, SCALE / s4.y, SCALE / s4.z, SCALE / s4.w};

    for (int n = ty; n < NN; n += 64) {
        float4 v = *(const float4*)(src + (size_t)n * DD);
        uint2 o;
        o.x = pack2(__expf(v.x - m4.x) * inv.x, __expf(v.y - m4.y) * inv.y);
        o.y = pack2(__expf(v.z - m4.z) * inv.z, __expf(v.w - m4.w) * inv.w);
        *(uint2*)(dst + (size_t)n * DW) = o;
    }
}

// ---------------------------------------------------------------------------
// ctx via tensor cores: ctx[sp][bh][d][e] = sum_{n in slice} Km[n,d]*V[n,e]
// ---------------------------------------------------------------------------
__global__ void __launch_bounds__(256) ctx_mma()
{
    __shared__ uint32_t cs[4][2048];   // 32KB: per stage [Km 1024w | V 1024w]
    const int bh = blockIdx.x, b = bh >> 4, h = bh & 15;
    const int n0 = blockIdx.y << 11;   // 2048 rows per split
    const int tid = threadIdx.x, lane = tid & 31, wid = tid >> 5;
    const int wd = wid >> 1, we = wid & 1;
    const uint32_t sbase = smem_u32(cs);

    const uint32_t* KmP = g_KmB + (size_t)b * NN * DW + h * 32;
    const uint32_t* VbP = g_Vb  + (size_t)b * NN * DW + h * 32;

    const int lop = tid >> 7, t7 = tid & 127;
    const int lrow = t7 >> 2, lc2 = (t7 & 3) << 1;
    const uint32_t* lsrc = (lop ? VbP : KmP) + (size_t)(n0 + lrow) * DW;
    const uint32_t d0 = sbase + (((lop << 10) + lrow * 32 + ((lc2       ^ (lrow & 7)) << 2)) << 2);
    const uint32_t d1 = sbase + (((lop << 10) + lrow * 32 + (((lc2 + 1) ^ (lrow & 7)) << 2)) << 2);

    auto issue = [&](int t) {
        const uint32_t so = (uint32_t)(t & 3) << 13;
        const uint32_t* s = lsrc + (size_t)(t << 5) * DW;
        CP_ASYNC16(d0 + so, s + (lc2 << 2));
        CP_ASYNC16(d1 + so, s + ((lc2 + 1) << 2));
    };

    const int arow = (lane & 7) | ((lane & 16) >> 1);
    const int achk = (wd << 1) + ((lane >> 3) & 1);
    const int brow = lane & 15;

    float acc[4][4];
    #pragma unroll
    for (int i = 0; i < 4; i++)
        #pragma unroll
        for (int j = 0; j < 4; j++) acc[i][j] = 0.f;

    auto compute = [&](int stg) {
        const uint32_t so = (uint32_t)stg << 13;
        #pragma unroll
        for (int ks = 0; ks < 2; ks++) {
            uint32_t af[4], bg[2][4];
            {
                const int r = (ks << 4) + arow;
                LDM_X4T(af, sbase + so + ((r * 32 + ((achk ^ (r & 7)) << 2)) << 2));
            }
            #pragma unroll
            for (int np = 0; np < 2; np++) {
                const int r = (ks << 4) + brow;
                const int c = (we << 2) + (np << 1) + (lane >> 4);
                LDM_X4T(bg[np], sbase + so + ((1024 + r * 32 + ((c ^ (r & 7)) << 2)) << 2));
            }
            #pragma unroll
            for (int nf = 0; nf < 4; nf++)
                MMA_BF16(acc[nf], af,
                         bg[nf >> 1][(nf & 1) << 1], bg[nf >> 1][((nf & 1) << 1) + 1]);
        }
    };

    issue(0); CP_COMMIT();
    issue(1); CP_COMMIT();
    issue(2); CP_COMMIT();
    for (int t = 0; t < 64; t++) {
        CP_WAIT2();
        __syncthreads();
        compute(t & 3);
        if (t + 3 < 64) issue(t + 3);
        CP_COMMIT();
    }

    float* o = g_ctx + (((size_t)blockIdx.y * (BB * HH) + bh) << 12);
    const int d = (wd << 4) + (lane >> 2);
    #pragma unroll
    for (int nf = 0; nf < 4; nf++) {
        const int e = (we << 5) + (nf << 3) + ((lane & 3) << 1);
        *(float2*)(o + d * 64 + e)       = make_float2(acc[nf][0], acc[nf][1]);
        *(float2*)(o + (d + 8) * 64 + e) = make_float2(acc[nf][2], acc[nf][3]);
    }
}

// ---------------------------------------------------------------------------
// Mbig^T packed: g_Mtb[b][n][k/2] = pack(sum_e ctx[b,h][d][e]*Wo[h*64+e][n])
// ---------------------------------------------------------------------------
__global__ void __launch_bounds__(256) mbig_kernel(const float* __restrict__ Wo)
{
    const int bh = blockIdx.x, b = bh >> 4, h = bh & 15;
    const int c0 = blockIdx.y << 6;

    __shared__ float csx[64][64];
    __shared__ float ws[64][64];
    const int tid = threadIdx.x;

    for (int i = tid; i < 4096; i += 256) {
        float sum = 0.f;
        #pragma unroll
        for (int sp = 0; sp < CTXSP; sp++)
            sum += g_ctx[(((size_t)sp * (BB * HH) + bh) << 12) + i];
        csx[i >> 6][i & 63] = sum;
    }
    for (int i = tid; i < 1024; i += 256) {
        int rr = i >> 4, cc = (i & 15) << 2;
        *(float4*)&ws[rr][cc] =
            *(const float4*)(Wo + (size_t)(h * DH + rr) * DD + c0 + cc);
    }
    __syncthreads();

    const int r0 = (tid >> 4) << 2, cc0 = (tid & 15) << 2;
    float acc[4][4] = {};
    #pragma unroll 16
    for (int k = 0; k < 64; k++) {
        float a[4], w[4];
        #pragma unroll
        for (int i = 0; i < 4; i++) a[i] = csx[r0 + i][k];
        *(float4*)w = *(float4*)&ws[k][cc0];
        #pragma unroll
        for (int i = 0; i < 4; i++)
            #pragma unroll
            for (int j = 0; j < 4; j++)
                acc[i][j] = fmaf(a[i], w[j], acc[i][j]);
    }
    uint32_t* ob = g_Mtb + ((size_t)b * DD * DW);
    const int kb2 = (h * DH + r0) >> 1;
    #pragma unroll
    for (int j = 0; j < 4; j++) {
        const size_t n = (size_t)(c0 + cc0 + j);
        ob[n * DW + kb2]     = pack2(acc[0][j], acc[1][j]);
        ob[n * DW + kb2 + 1] = pack2(acc[2][j], acc[3][j]);
    }
}

// ---------------------------------------------------------------------------
// Launcher. Inputs: 0:x 1:Wq 2:bq 3:Wk(dead) 4:bk(dead) 5:Wv 6:bv 7:Wo 8:bo
// ---------------------------------------------------------------------------
extern "C" void kernel_launch(void* const* d_in, const int* in_sizes, int n_in,
                              void* d_out, int out_size)
{
    const float* x  = (const float*)d_in[0];
    const float* Wq = (const float*)d_in[1];
    const float* bq = (const float*)d_in[2];
    const float* Wv = (const float*)d_in[5];
    const float* bv = (const float*)d_in[6];
    const float* Wo = (const float*)d_in[7];
    const float* bo = (const float*)d_in[8];
    float* out = (float*)d_out;

    float* Q;
    uint32_t *xb, *Qb, *Vb, *Wqb, *Wvb, *Mtb;
    cudaGetSymbolAddress((void**)&Q,   g_Q);
    cudaGetSymbolAddress((void**)&xb,  g_xb);
    cudaGetSymbolAddress((void**)&Qb,  g_Qb);
    cudaGetSymbolAddress((void**)&Vb,  g_Vb);
    cudaGetSymbolAddress((void**)&Wqb, g_Wqb);
    cudaGetSymbolAddress((void**)&Wvb, g_Wvb);
    cudaGetSymbolAddress((void**)&Mtb, g_Mtb);

    cudaFuncSetAttribute((const void*)gemm_bf16<0>,
                         cudaFuncAttributeMaxDynamicSharedMemorySize, GEMM_SMEM);
    cudaFuncSetAttribute((const void*)gemm_bf16<1>,
                         cudaFuncAttributeMaxDynamicSharedMemorySize, GEMM_SMEM);
    cudaFuncSetAttribute((const void*)gemm_bf16<2>,
                         cudaFuncAttributeMaxDynamicSharedMemorySize, GEMM_SMEM);

    const long long sXW = (long long)NN * DW;
    const long long sXD = (long long)NN * DD;
    dim3 ggrid(DD / 128, NN / 256, BB);

    pack_rows<<<(BB * NN * DD) / (256 * 8), 256>>>(x, xb);
    pack_w<<<dim3(DD / 32, DD / 64), 256>>>(Wq, Wqb);
    pack_w<<<dim3(DD / 32, DD / 64), 256>>>(Wv, Wvb);

    // Q = softmax(x@Wq + bq) * s  (fused warp-internal epilogue)
    gemm_bf16<1><<<ggrid, 256, GEMM_SMEM>>>(xb, Wqb, bq, Q, Qb, sXW, 0, sXD);
    // V = x@Wv + bv  (packed bf16 only)
    gemm_bf16<2><<<ggrid, 256, GEMM_SMEM>>>(xb, Wvb, bv, Q, Vb, sXW, 0, sXD);

    // Km = softmax(Qs, seq) * s  (packed bf16)
    col_softmax<<<dim3(DD / 32, BB), 512>>>();

    // ctx partials (tensor cores), then Mbig^T packed
    ctx_mma<<<dim3(BB * HH, CTXSP), 256>>>();
    mbig_kernel<<<dim3(BB * HH, DD / 64), 256>>>(Wo);

    // out[b] = Qs[b] @ Mbig[b] + bo
    gemm_bf16<0><<<ggrid, 256, GEMM_SMEM>>>(Qb, Mtb, bo, out, Qb,
                                            sXW, (long long)DD * DW, sXD);
}

// round 10
// speedup vs baseline: 1.4587x; 1.4587x over previous
#include <cuda_runtime.h>
#include <cstdint>

// Shapes fixed: B=4, N=4096, D=1024, H=16, d_head=64.
#define BB 4
#define NN 4096
#define DD 1024
#define DW 512            // packed bf16x2 words per row of 1024
#define HH 16
#define DH 64
#define CTXSP 4
#define SCALE 0.5946035575013605f   // (d_head^0.5)^(-0.25) = 2^(-0.75)

// Scratch (__device__ globals; no cudaMalloc allowed).
__device__ float    g_Q  [(size_t)BB * NN * DD];   // Q proj, row-softmaxed (fp32, for col_softmax)
__device__ float    g_ctx[(size_t)CTXSP * BB * HH * DH * DH];
__device__ uint32_t g_xb [(size_t)BB * NN * DW];   // x packed bf16
__device__ uint32_t g_Qb [(size_t)BB * NN * DW];   // softmaxed Q packed bf16
__device__ uint32_t g_Vb [(size_t)BB * NN * DW];   // V proj packed bf16
__device__ uint32_t g_KmB[(size_t)BB * NN * DW];   // column-softmax packed bf16
__device__ uint32_t g_Wqb[(size_t)DD * DW];        // Wq^T packed bf16
__device__ uint32_t g_Wvb[(size_t)DD * DW];        // Wv^T packed bf16
__device__ uint32_t g_Mtb[(size_t)BB * DD * DW];   // Mbig^T packed bf16

// ---------------------------------------------------------------------------
// helpers
// ---------------------------------------------------------------------------
__device__ __forceinline__ uint32_t smem_u32(const void* p) {
    uint32_t a;
    asm("{ .reg .u64 t; cvta.to.shared.u64 t, %1; cvt.u32.u64 %0, t; }" : "=r"(a) : "l"(p));
    return a;
}
__device__ __forceinline__ uint32_t pack2(float lo, float hi) {
    uint32_t r;
    asm("cvt.rn.bf16x2.f32 %0, %1, %2;" : "=r"(r) : "f"(hi), "f"(lo));
    return r;
}
#define CP_ASYNC16(dst, src) \
    asm volatile("cp.async.cg.shared.global [%0], [%1], 16;" :: "r"(dst), "l"(src) : "memory")
#define CP_COMMIT()  asm volatile("cp.async.commit_group;" ::: "memory")
#define CP_WAIT2()   asm volatile("cp.async.wait_group 2;" ::: "memory")

#define LDM_X4(r, a)                                                            \
    asm volatile("ldmatrix.sync.aligned.m8n8.x4.shared.b16 {%0,%1,%2,%3}, [%4];"\
        : "=r"((r)[0]), "=r"((r)[1]), "=r"((r)[2]), "=r"((r)[3]) : "r"(a))
#define LDM_X4T(r, a)                                                           \
    asm volatile("ldmatrix.sync.aligned.m8n8.x4.trans.shared.b16 {%0,%1,%2,%3}, [%4];"\
        : "=r"((r)[0]), "=r"((r)[1]), "=r"((r)[2]), "=r"((r)[3]) : "r"(a))
#define MMA_BF16(d, a, b0, b1)                                                  \
    asm volatile("mma.sync.aligned.m16n8k16.row.col.f32.bf16.bf16.f32 "         \
        "{%0,%1,%2,%3}, {%4,%5,%6,%7}, {%8,%9}, {%0,%1,%2,%3};"                 \
        : "+f"((d)[0]), "+f"((d)[1]), "+f"((d)[2]), "+f"((d)[3])                \
        : "r"((a)[0]), "r"((a)[1]), "r"((a)[2]), "r"((a)[3]), "r"(b0), "r"(b1))

// ---------------------------------------------------------------------------
// bf16 mma.sync GEMM (R8-exact geometry: empirically optimal on this path).
// MODE 0: C=fp32+bias.  MODE 1: row-softmax(+bias) over 64-col heads, fp32 C
// AND packed Cb.  MODE 2: bias, packed Cb only.
// CTA 128x128, 8 warps 2(m) x 4(n), K-chunk 32 bf16, 4-stage cp.async ring,
// 2 CTAs/SM (128-reg cap) -- cross-CTA overlap hides sync/wait latency.
// ---------------------------------------------------------------------------
#define GEMM_SMEM 65536

template <int MODE>
__global__ void __launch_bounds__(256, 2)
gemm_bf16(const uint32_t* __restrict__ A, const uint32_t* __restrict__ Bt,
          const float* __restrict__ bias, float* __restrict__ C,
          uint32_t* __restrict__ Cb,
          long long sA, long long sB, long long sC)
{
    extern __shared__ uint32_t sm[];

    const int b = blockIdx.z;
    A  += (long long)b * sA;
    Bt += (long long)b * sB;
    C  += (long long)b * sC;
    Cb += (long long)b * NN * DW;
    const int n0 = blockIdx.x << 7;
    const int m0 = blockIdx.y << 7;
    const int tid = threadIdx.x, lane = tid & 31, wid = tid >> 5;
    const int wm = wid >> 2, wn = wid & 3;

    const uint32_t sbase = smem_u32(sm);

    const int lr  = tid >> 1;
    const int lk8 = (tid & 1) << 3;
    const uint32_t* Ap = A  + (long long)(m0 + lr) * DW + lk8;
    const uint32_t* Bp = Bt + (long long)(n0 + lr) * DW + lk8;
    const int lswz = (lr >> 1) & 3;
    const int cb   = lk8 >> 2;
    const uint32_t stA0 = sbase + (lr << 6) + ((cb ^ lswz) << 4);
    const uint32_t stA1 = sbase + (lr << 6) + (((cb + 1) ^ lswz) << 4);

    auto issue = [&](int t) {
        const uint32_t so = (uint32_t)(t & 3) << 14;
        const uint32_t* a  = Ap + (t << 4);
        const uint32_t* bb = Bp + (t << 4);
        CP_ASYNC16(stA0 + so,         a);
        CP_ASYNC16(stA1 + so,         a + 4);
        CP_ASYNC16(stA0 + so + 8192u, bb);
        CP_ASYNC16(stA1 + so + 8192u, bb + 4);
    };

    const int ar16 = lane & 15;
    const int acs  = lane >> 4;
    const int aswz = (ar16 >> 1) & 3;
    const int br16 = (lane & 7) | ((lane & 16) >> 1);
    const int bcs  = (lane >> 3) & 1;
    const int bswz = (br16 >> 1) & 3;

    float acc[4][4][4];
    #pragma unroll
    for (int i = 0; i < 4; i++)
        #pragma unroll
        for (int j = 0; j < 4; j++)
            #pragma unroll
            for (int r = 0; r < 4; r++) acc[i][j][r] = 0.f;

    auto compute = [&](int stg) {
        const uint32_t so = (uint32_t)stg << 14;
        const uint32_t abase = sbase + so + (((wm << 6) + ar16) << 6);
        const uint32_t bbase = sbase + so + 8192u + (((wn << 5) + br16) << 6);
        #pragma unroll
        for (int ks = 0; ks < 2; ks++) {
            uint32_t af[4][4], bg[2][4];
            const uint32_t ac = (uint32_t)((((ks << 1) + acs) ^ aswz) << 4);
            const uint32_t bc = (uint32_t)((((ks << 1) + bcs) ^ bswz) << 4);
            #pragma unroll
            for (int mf = 0; mf < 4; mf++)
                LDM_X4(af[mf], abase + (uint32_t)(mf << 10) + ac);
            #pragma unroll
            for (int np = 0; np < 2; np++)
                LDM_X4(bg[np], bbase + (uint32_t)(np << 10) + bc);
            #pragma unroll
            for (int mf = 0; mf < 4; mf++)
                #pragma unroll
                for (int nf = 0; nf < 4; nf++)
                    MMA_BF16(acc[mf][nf], af[mf],
                             bg[nf >> 1][(nf & 1) << 1], bg[nf >> 1][((nf & 1) << 1) + 1]);
        }
    };

    issue(0); CP_COMMIT();
    issue(1); CP_COMMIT();
    issue(2); CP_COMMIT();
    for (int t = 0; t < 32; t++) {
        CP_WAIT2();
        __syncthreads();
        compute(t & 3);
        if (t + 3 < 32) issue(t + 3);
        CP_COMMIT();
    }

    // ---- epilogue ----------------------------------------------------------
    const int cbase = n0 + (wn << 5);
    float2 bv[4];
    #pragma unroll
    for (int nf = 0; nf < 4; nf++)
        bv[nf] = *(const float2*)(bias + cbase + (nf << 3) + ((lane & 3) << 1));
    #pragma unroll
    for (int mf = 0; mf < 4; mf++)
        #pragma unroll
        for (int nf = 0; nf < 4; nf++) {
            acc[mf][nf][0] += bv[nf].x; acc[mf][nf][1] += bv[nf].y;
            acc[mf][nf][2] += bv[nf].x; acc[mf][nf][3] += bv[nf].y;
        }

    if (MODE == 1) {
        // row softmax over the 64-col head (this warp + partner wn^1), *SCALE.
        float* sred = (float*)sm;        // [wm*4+wn][2][64] floats = 4KB
        const int me = (wm << 2) + wn, pr = (wm << 2) + (wn ^ 1);
        #pragma unroll
        for (int mf = 0; mf < 4; mf++)
            #pragma unroll
            for (int half = 0; half < 2; half++) {
                float mx = acc[mf][0][half * 2];
                #pragma unroll
                for (int nf = 0; nf < 4; nf++) {
                    mx = fmaxf(mx, acc[mf][nf][half * 2]);
                    mx = fmaxf(mx, acc[mf][nf][half * 2 + 1]);
                }
                mx = fmaxf(mx, __shfl_xor_sync(0xffffffffu, mx, 1));
                mx = fmaxf(mx, __shfl_xor_sync(0xffffffffu, mx, 2));
                if ((lane & 3) == 0)
                    sred[(me * 2 + 0) * 64 + (mf << 4) + (lane >> 2) + half * 8] = mx;
            }
        __syncthreads();
        #pragma unroll
        for (int mf = 0; mf < 4; mf++)
            #pragma unroll
            for (int half = 0; half < 2; half++) {
                const int row = (mf << 4) + (lane >> 2) + half * 8;
                const float m = fmaxf(sred[(me * 2 + 0) * 64 + row],
                                      sred[(pr * 2 + 0) * 64 + row]);
                float s = 0.f;
                #pragma unroll
                for (int nf = 0; nf < 4; nf++) {
                    acc[mf][nf][half * 2]     = __expf(acc[mf][nf][half * 2]     - m);
                    acc[mf][nf][half * 2 + 1] = __expf(acc[mf][nf][half * 2 + 1] - m);
                    s += acc[mf][nf][half * 2] + acc[mf][nf][half * 2 + 1];
                }
                s += __shfl_xor_sync(0xffffffffu, s, 1);
                s += __shfl_xor_sync(0xffffffffu, s, 2);
                if ((lane & 3) == 0) sred[(me * 2 + 1) * 64 + row] = s;
            }
        __syncthreads();
        #pragma unroll
        for (int mf = 0; mf < 4; mf++)
            #pragma unroll
            for (int half = 0; half < 2; half++) {
                const int row = (mf << 4) + (lane >> 2) + half * 8;
                const float s = sred[(me * 2 + 1) * 64 + row] +
                                sred[(pr * 2 + 1) * 64 + row];
                const float inv = SCALE / s;
                #pragma unroll
                for (int nf = 0; nf < 4; nf++) {
                    acc[mf][nf][half * 2]     *= inv;
                    acc[mf][nf][half * 2 + 1] *= inv;
                }
            }
    }

    #pragma unroll
    for (int mf = 0; mf < 4; mf++) {
        const int r0 = m0 + (wm << 6) + (mf << 4) + (lane >> 2);
        #pragma unroll
        for (int nf = 0; nf < 4; nf++) {
            const int co = (nf << 3) + ((lane & 3) << 1);
            if (MODE != 2) {
                float* Cp = C + (long long)r0 * DD + cbase + co;
                *(float2*)Cp             = make_float2(acc[mf][nf][0], acc[mf][nf][1]);
                *(float2*)(Cp + 8LL*DD)  = make_float2(acc[mf][nf][2], acc[mf][nf][3]);
            }
            if (MODE != 0) {
                const int w = (cbase >> 1) + (nf << 2) + (lane & 3);
                Cb[(size_t)r0 * DW + w]       = pack2(acc[mf][nf][0], acc[mf][nf][1]);
                Cb[(size_t)(r0 + 8) * DW + w] = pack2(acc[mf][nf][2], acc[mf][nf][3]);
            }
        }
    }
}

// ---------------------------------------------------------------------------
// pack_w: W[k][n] -> Wtb[n][k/2] packed bf16 (transpose + pack)
// ---------------------------------------------------------------------------
__global__ void __launch_bounds__(256) pack_w(const float* __restrict__ W,
                                              uint32_t* __restrict__ Wtb)
{
    __shared__ float s[64][36];
    const int n0 = blockIdx.x << 5, k0 = blockIdx.y << 6;
    const int tid = threadIdx.x;
    {
        const int i = tid >> 2, j8 = (tid & 3) << 3;
        *(float4*)&s[i][j8]     = *(const float4*)(W + (size_t)(k0 + i) * DD + n0 + j8);
        *(float4*)&s[i][j8 + 4] = *(const float4*)(W + (size_t)(k0 + i) * DD + n0 + j8 + 4);
    }
    __syncthreads();
    const int nl = tid >> 3, kg = tid & 7;
    uint4 o;
    o.x = pack2(s[kg * 8 + 0][nl], s[kg * 8 + 1][nl]);
    o.y = pack2(s[kg * 8 + 2][nl], s[kg * 8 + 3][nl]);
    o.z = pack2(s[kg * 8 + 4][nl], s[kg * 8 + 5][nl]);
    o.w = pack2(s[kg * 8 + 6][nl], s[kg * 8 + 7][nl]);
    *(uint4*)(Wtb + (size_t)(n0 + nl) * DW + (k0 >> 1) + (kg << 2)) = o;
}

// ---------------------------------------------------------------------------
// pack_rows: fp32 row-major -> packed bf16
// ---------------------------------------------------------------------------
__global__ void __launch_bounds__(256) pack_rows(const float* __restrict__ src,
                                                 uint32_t* __restrict__ dst)
{
    const size_t q = ((size_t)blockIdx.x * 256 + threadIdx.x) << 3;
    float4 a = *(const float4*)(src + q), b = *(const float4*)(src + q + 4);
    uint4 o = {pack2(a.x, a.y), pack2(a.z, a.w), pack2(b.x, b.y), pack2(b.z, b.w)};
    *(uint4*)(dst + (q >> 1)) = o;
}

// ---------------------------------------------------------------------------
// Column softmax over seq dim N -> packed bf16 g_KmB.  32 cols/CTA.
// Input is row-softmaxed Q: every value is in [0, SCALE] (bounded!), so the
// max-subtraction is a mathematical no-op -> 2 passes instead of 3.
// ---------------------------------------------------------------------------
__global__ void __launch_bounds__(512) col_softmax()
{
    const int b  = blockIdx.y;
    const int c0 = blockIdx.x << 5;
    const int tx = threadIdx.x & 7;
    const int ty = threadIdx.x >> 3;
    const float* src = g_Q + (size_t)b * NN * DD + c0 + (tx << 2);
    uint32_t*    dst = g_KmB + (size_t)b * NN * DW + (c0 >> 1) + (tx << 1);

    __shared__ float4 red[64][8];

    float4 s4 = {0.f, 0.f, 0.f, 0.f};
    for (int n = ty; n < NN; n += 64) {
        float4 v = *(const float4*)(src + (size_t)n * DD);
        s4.x += __expf(v.x); s4.y += __expf(v.y);
        s4.z += __expf(v.z); s4.w += __expf(v.w);
    }
    red[ty][tx] = s4;
    __syncthreads();
    s4.x = 0.f; s4.y = 0.f; s4.z = 0.f; s4.w = 0.f;
    #pragma unroll 8
    for (int i = 0; i < 64; i++) {
        float4 r = red[i][tx];
        s4.x += r.x; s4.y += r.y; s4.z += r.z; s4.w += r.w;
    }
    const float4 inv = {SCALE / s4.x, SCALE / s4.y, SCALE / s4.z, SCALE / s4.w};

    for (int n = ty; n < NN; n += 64) {
        float4 v = *(const float4*)(src + (size_t)n * DD);
        uint2 o;
        o.x = pack2(__expf(v.x) * inv.x, __expf(v.y) * inv.y);
        o.y = pack2(__expf(v.z) * inv.z, __expf(v.w) * inv.w);
        *(uint2*)(dst + (size_t)n * DW) = o;
    }
}

// ---------------------------------------------------------------------------
// ctx via tensor cores: ctx[sp][bh][d][e] = sum_{n in slice} Km[n,d]*V[n,e]
// CTXSP=4 splits (1024 rows each) -> 256 CTAs, 2 balanced waves on 148 SMs.
// ---------------------------------------------------------------------------
__global__ void __launch_bounds__(256) ctx_mma()
{
    __shared__ uint32_t cs[4][2048];   // 32KB: per stage [Km 1024w | V 1024w]
    const int bh = blockIdx.x, b = bh >> 4, h = bh & 15;
    const int n0 = blockIdx.y << 10;   // 1024 rows per split
    const int tid = threadIdx.x, lane = tid & 31, wid = tid >> 5;
    const int wd = wid >> 1, we = wid & 1;
    const uint32_t sbase = smem_u32(cs);

    const uint32_t* KmP = g_KmB + (size_t)b * NN * DW + h * 32;
    const uint32_t* VbP = g_Vb  + (size_t)b * NN * DW + h * 32;

    const int lop = tid >> 7, t7 = tid & 127;
    const int lrow = t7 >> 2, lc2 = (t7 & 3) << 1;
    const uint32_t* lsrc = (lop ? VbP : KmP) + (size_t)(n0 + lrow) * DW;
    const uint32_t d0 = sbase + (((lop << 10) + lrow * 32 + ((lc2       ^ (lrow & 7)) << 2)) << 2);
    const uint32_t d1 = sbase + (((lop << 10) + lrow * 32 + (((lc2 + 1) ^ (lrow & 7)) << 2)) << 2);

    auto issue = [&](int t) {
        const uint32_t so = (uint32_t)(t & 3) << 13;
        const uint32_t* s = lsrc + (size_t)(t << 5) * DW;
        CP_ASYNC16(d0 + so, s + (lc2 << 2));
        CP_ASYNC16(d1 + so, s + ((lc2 + 1) << 2));
    };

    const int arow = (lane & 7) | ((lane & 16) >> 1);
    const int achk = (wd << 1) + ((lane >> 3) & 1);
    const int brow = lane & 15;

    float acc[4][4];
    #pragma unroll
    for (int i = 0; i < 4; i++)
        #pragma unroll
        for (int j = 0; j < 4; j++) acc[i][j] = 0.f;

    auto compute = [&](int stg) {
        const uint32_t so = (uint32_t)stg << 13;
        #pragma unroll
        for (int ks = 0; ks < 2; ks++) {
            uint32_t af[4], bg[2][4];
            {
                const int r = (ks << 4) + arow;
                LDM_X4T(af, sbase + so + ((r * 32 + ((achk ^ (r & 7)) << 2)) << 2));
            }
            #pragma unroll
            for (int np = 0; np < 2; np++) {
                const int r = (ks << 4) + brow;
                const int c = (we << 2) + (np << 1) + (lane >> 4);
                LDM_X4T(bg[np], sbase + so + ((1024 + r * 32 + ((c ^ (r & 7)) << 2)) << 2));
            }
            #pragma unroll
            for (int nf = 0; nf < 4; nf++)
                MMA_BF16(acc[nf], af,
                         bg[nf >> 1][(nf & 1) << 1], bg[nf >> 1][((nf & 1) << 1) + 1]);
        }
    };

    issue(0); CP_COMMIT();
    issue(1); CP_COMMIT();
    issue(2); CP_COMMIT();
    for (int t = 0; t < 32; t++) {
        CP_WAIT2();
        __syncthreads();
        compute(t & 3);
        if (t + 3 < 32) issue(t + 3);
        CP_COMMIT();
    }

    float* o = g_ctx + (((size_t)blockIdx.y * (BB * HH) + bh) << 12);
    const int d = (wd << 4) + (lane >> 2);
    #pragma unroll
    for (int nf = 0; nf < 4; nf++) {
        const int e = (we << 5) + (nf << 3) + ((lane & 3) << 1);
        *(float2*)(o + d * 64 + e)       = make_float2(acc[nf][0], acc[nf][1]);
        *(float2*)(o + (d + 8) * 64 + e) = make_float2(acc[nf][2], acc[nf][3]);
    }
}

// ---------------------------------------------------------------------------
// Mbig^T packed: g_Mtb[b][n][k/2] = pack(sum_e ctx[b,h][d][e]*Wo[h*64+e][n])
// ---------------------------------------------------------------------------
__global__ void __launch_bounds__(256) mbig_kernel(const float* __restrict__ Wo)
{
    const int bh = blockIdx.x, b = bh >> 4, h = bh & 15;
    const int c0 = blockIdx.y << 6;

    __shared__ float csx[64][64];
    __shared__ float ws[64][64];
    const int tid = threadIdx.x;

    for (int i = tid; i < 4096; i += 256) {
        float sum = 0.f;
        #pragma unroll
        for (int sp = 0; sp < CTXSP; sp++)
            sum += g_ctx[(((size_t)sp * (BB * HH) + bh) << 12) + i];
        csx[i >> 6][i & 63] = sum;
    }
    for (int i = tid; i < 1024; i += 256) {
        int rr = i >> 4, cc = (i & 15) << 2;
        *(float4*)&ws[rr][cc] =
            *(const float4*)(Wo + (size_t)(h * DH + rr) * DD + c0 + cc);
    }
    __syncthreads();

    const int r0 = (tid >> 4) << 2, cc0 = (tid & 15) << 2;
    float acc[4][4] = {};
    #pragma unroll 16
    for (int k = 0; k < 64; k++) {
        float a[4], w[4];
        #pragma unroll
        for (int i = 0; i < 4; i++) a[i] = csx[r0 + i][k];
        *(float4*)w = *(float4*)&ws[k][cc0];
        #pragma unroll
        for (int i = 0; i < 4; i++)
            #pragma unroll
            for (int j = 0; j < 4; j++)
                acc[i][j] = fmaf(a[i], w[j], acc[i][j]);
    }
    uint32_t* ob = g_Mtb + ((size_t)b * DD * DW);
    const int kb2 = (h * DH + r0) >> 1;
    #pragma unroll
    for (int j = 0; j < 4; j++) {
        const size_t n = (size_t)(c0 + cc0 + j);
        ob[n * DW + kb2]     = pack2(acc[0][j], acc[1][j]);
        ob[n * DW + kb2 + 1] = pack2(acc[2][j], acc[3][j]);
    }
}

// ---------------------------------------------------------------------------
// Launcher. Inputs: 0:x 1:Wq 2:bq 3:Wk(dead) 4:bk(dead) 5:Wv 6:bv 7:Wo 8:bo
// ---------------------------------------------------------------------------
extern "C" void kernel_launch(void* const* d_in, const int* in_sizes, int n_in,
                              void* d_out, int out_size)
{
    const float* x  = (const float*)d_in[0];
    const float* Wq = (const float*)d_in[1];
    const float* bq = (const float*)d_in[2];
    const float* Wv = (const float*)d_in[5];
    const float* bv = (const float*)d_in[6];
    const float* Wo = (const float*)d_in[7];
    const float* bo = (const float*)d_in[8];
    float* out = (float*)d_out;

    float* Q;
    uint32_t *xb, *Qb, *Vb, *Wqb, *Wvb, *Mtb;
    cudaGetSymbolAddress((void**)&Q,   g_Q);
    cudaGetSymbolAddress((void**)&xb,  g_xb);
    cudaGetSymbolAddress((void**)&Qb,  g_Qb);
    cudaGetSymbolAddress((void**)&Vb,  g_Vb);
    cudaGetSymbolAddress((void**)&Wqb, g_Wqb);
    cudaGetSymbolAddress((void**)&Wvb, g_Wvb);
    cudaGetSymbolAddress((void**)&Mtb, g_Mtb);

    cudaFuncSetAttribute((const void*)gemm_bf16<0>,
                         cudaFuncAttributeMaxDynamicSharedMemorySize, GEMM_SMEM);
    cudaFuncSetAttribute((const void*)gemm_bf16<1>,
                         cudaFuncAttributeMaxDynamicSharedMemorySize, GEMM_SMEM);
    cudaFuncSetAttribute((const void*)gemm_bf16<2>,
                         cudaFuncAttributeMaxDynamicSharedMemorySize, GEMM_SMEM);

    const long long sXW = (long long)NN * DW;
    const long long sXD = (long long)NN * DD;
    dim3 ggrid(DD / 128, NN / 128, BB);

    pack_rows<<<(BB * NN * DD) / (256 * 8), 256>>>(x, xb);
    pack_w<<<dim3(DD / 32, DD / 64), 256>>>(Wq, Wqb);
    pack_w<<<dim3(DD / 32, DD / 64), 256>>>(Wv, Wvb);

    // Q = softmax(x@Wq + bq) * s  (fused epilogue; fp32 + packed)
    gemm_bf16<1><<<ggrid, 256, GEMM_SMEM>>>(xb, Wqb, bq, Q, Qb, sXW, 0, sXD);
    // V = x@Wv + bv  (packed bf16 only)
    gemm_bf16<2><<<ggrid, 256, GEMM_SMEM>>>(xb, Wvb, bv, Q, Vb, sXW, 0, sXD);

    // Km = softmax(Qs, seq) * s  (packed bf16; 2-pass, values bounded)
    col_softmax<<<dim3(DD / 32, BB), 512>>>();

    // ctx partials (tensor cores), then Mbig^T packed
    ctx_mma<<<dim3(BB * HH, CTXSP), 256>>>();
    mbig_kernel<<<dim3(BB * HH, DD / 64), 256>>>(Wo);

    // out[b] = Qs[b] @ Mbig[b] + bo
    gemm_bf16<0><<<ggrid, 256, GEMM_SMEM>>>(Qb, Mtb, bo, out, Qb,
                                            sXW, (long long)DD * DW, sXD);
}

// round 12
// speedup vs baseline: 1.5375x; 1.0540x over previous
#include <cuda_runtime.h>
#include <cstdint>

// Shapes fixed: B=4, N=4096, D=1024, H=16, d_head=64.
#define BB 4
#define NN 4096
#define DD 1024
#define DW 512            // packed bf16x2 words per row of 1024
#define HH 16
#define DH 64
#define CTXSP 4
#define SCALE 0.5946035575013605f   // (d_head^0.5)^(-0.25) = 2^(-0.75)

// Scratch (__device__ globals; no cudaMalloc allowed).
__device__ float    g_ctx[(size_t)CTXSP * BB * HH * DH * DH];
__device__ uint32_t g_xb [(size_t)BB * NN * DW];   // x packed bf16
__device__ uint32_t g_Qb [(size_t)BB * NN * DW];   // softmaxed Q packed bf16
__device__ uint32_t g_Vb [(size_t)BB * NN * DW];   // V proj packed bf16
__device__ uint32_t g_KmB[(size_t)BB * NN * DW];   // column-softmax packed bf16
__device__ uint32_t g_Wqb[(size_t)DD * DW];        // Wq^T packed bf16
__device__ uint32_t g_Wvb[(size_t)DD * DW];        // Wv^T packed bf16
__device__ uint32_t g_Mtb[(size_t)BB * DD * DW];   // Mbig^T packed bf16

// ---------------------------------------------------------------------------
// helpers
// ---------------------------------------------------------------------------
__device__ __forceinline__ uint32_t smem_u32(const void* p) {
    uint32_t a;
    asm("{ .reg .u64 t; cvta.to.shared.u64 t, %1; cvt.u32.u64 %0, t; }" : "=r"(a) : "l"(p));
    return a;
}
__device__ __forceinline__ uint32_t pack2(float lo, float hi) {
    uint32_t r;
    asm("cvt.rn.bf16x2.f32 %0, %1, %2;" : "=r"(r) : "f"(hi), "f"(lo));
    return r;
}
__device__ __forceinline__ float bf_lo(uint32_t w) { return __uint_as_float(w << 16); }
__device__ __forceinline__ float bf_hi(uint32_t w) { return __uint_as_float(w & 0xffff0000u); }

#define CP_ASYNC16(dst, src) \
    asm volatile("cp.async.cg.shared.global [%0], [%1], 16;" :: "r"(dst), "l"(src) : "memory")
#define CP_COMMIT()  asm volatile("cp.async.commit_group;" ::: "memory")
#define CP_WAIT2()   asm volatile("cp.async.wait_group 2;" ::: "memory")

#define LDM_X4(r, a)                                                            \
    asm volatile("ldmatrix.sync.aligned.m8n8.x4.shared.b16 {%0,%1,%2,%3}, [%4];"\
        : "=r"((r)[0]), "=r"((r)[1]), "=r"((r)[2]), "=r"((r)[3]) : "r"(a))
#define LDM_X4T(r, a)                                                           \
    asm volatile("ldmatrix.sync.aligned.m8n8.x4.trans.shared.b16 {%0,%1,%2,%3}, [%4];"\
        : "=r"((r)[0]), "=r"((r)[1]), "=r"((r)[2]), "=r"((r)[3]) : "r"(a))
#define MMA_BF16(d, a, b0, b1)                                                  \
    asm volatile("mma.sync.aligned.m16n8k16.row.col.f32.bf16.bf16.f32 "         \
        "{%0,%1,%2,%3}, {%4,%5,%6,%7}, {%8,%9}, {%0,%1,%2,%3};"                 \
        : "+f"((d)[0]), "+f"((d)[1]), "+f"((d)[2]), "+f"((d)[3])                \
        : "r"((a)[0]), "r"((a)[1]), "r"((a)[2]), "r"((a)[3]), "r"(b0), "r"(b1))

// ---------------------------------------------------------------------------
// bf16 mma.sync GEMM (R8/R10 geometry: empirically optimal on this path).
// MODE 0: C=fp32+bias.  MODE 1: row-softmax(+bias) over 64-col heads,
// packed Cb ONLY (fp32 Q no longer needed).  MODE 2: bias, packed Cb only.
// CTA 128x128, 8 warps 2(m) x 4(n), K-chunk 32 bf16, 4-stage cp.async ring,
// 2 CTAs/SM (128-reg cap) -- cross-CTA overlap hides sync/wait latency.
// ---------------------------------------------------------------------------
#define GEMM_SMEM 65536

template <int MODE>
__global__ void __launch_bounds__(256, 2)
gemm_bf16(const uint32_t* __restrict__ A, const uint32_t* __restrict__ Bt,
          const float* __restrict__ bias, float* __restrict__ C,
          uint32_t* __restrict__ Cb,
          long long sA, long long sB, long long sC)
{
    extern __shared__ uint32_t sm[];

    const int b = blockIdx.z;
    A  += (long long)b * sA;
    Bt += (long long)b * sB;
    C  += (long long)b * sC;
    Cb += (long long)b * NN * DW;
    const int n0 = blockIdx.x << 7;
    const int m0 = blockIdx.y << 7;
    const int tid = threadIdx.x, lane = tid & 31, wid = tid >> 5;
    const int wm = wid >> 2, wn = wid & 3;

    const uint32_t sbase = smem_u32(sm);

    const int lr  = tid >> 1;
    const int lk8 = (tid & 1) << 3;
    const uint32_t* Ap = A  + (long long)(m0 + lr) * DW + lk8;
    const uint32_t* Bp = Bt + (long long)(n0 + lr) * DW + lk8;
    const int lswz = (lr >> 1) & 3;
    const int cb   = lk8 >> 2;
    const uint32_t stA0 = sbase + (lr << 6) + ((cb ^ lswz) << 4);
    const uint32_t stA1 = sbase + (lr << 6) + (((cb + 1) ^ lswz) << 4);

    auto issue = [&](int t) {
        const uint32_t so = (uint32_t)(t & 3) << 14;
        const uint32_t* a  = Ap + (t << 4);
        const uint32_t* bb = Bp + (t << 4);
        CP_ASYNC16(stA0 + so,         a);
        CP_ASYNC16(stA1 + so,         a + 4);
        CP_ASYNC16(stA0 + so + 8192u, bb);
        CP_ASYNC16(stA1 + so + 8192u, bb + 4);
    };

    const int ar16 = lane & 15;
    const int acs  = lane >> 4;
    const int aswz = (ar16 >> 1) & 3;
    const int br16 = (lane & 7) | ((lane & 16) >> 1);
    const int bcs  = (lane >> 3) & 1;
    const int bswz = (br16 >> 1) & 3;

    float acc[4][4][4];
    #pragma unroll
    for (int i = 0; i < 4; i++)
        #pragma unroll
        for (int j = 0; j < 4; j++)
            #pragma unroll
            for (int r = 0; r < 4; r++) acc[i][j][r] = 0.f;

    auto compute = [&](int stg) {
        const uint32_t so = (uint32_t)stg << 14;
        const uint32_t abase = sbase + so + (((wm << 6) + ar16) << 6);
        const uint32_t bbase = sbase + so + 8192u + (((wn << 5) + br16) << 6);
        #pragma unroll
        for (int ks = 0; ks < 2; ks++) {
            uint32_t af[4][4], bg[2][4];
            const uint32_t ac = (uint32_t)((((ks << 1) + acs) ^ aswz) << 4);
            const uint32_t bc = (uint32_t)((((ks << 1) + bcs) ^ bswz) << 4);
            #pragma unroll
            for (int mf = 0; mf < 4; mf++)
                LDM_X4(af[mf], abase + (uint32_t)(mf << 10) + ac);
            #pragma unroll
            for (int np = 0; np < 2; np++)
                LDM_X4(bg[np], bbase + (uint32_t)(np << 10) + bc);
            #pragma unroll
            for (int mf = 0; mf < 4; mf++)
                #pragma unroll
                for (int nf = 0; nf < 4; nf++)
                    MMA_BF16(acc[mf][nf], af[mf],
                             bg[nf >> 1][(nf & 1) << 1], bg[nf >> 1][((nf & 1) << 1) + 1]);
        }
    };

    issue(0); CP_COMMIT();
    issue(1); CP_COMMIT();
    issue(2); CP_COMMIT();
    for (int t = 0; t < 32; t++) {
        CP_WAIT2();
        __syncthreads();
        compute(t & 3);
        if (t + 3 < 32) issue(t + 3);
        CP_COMMIT();
    }

    // ---- epilogue ----------------------------------------------------------
    const int cbase = n0 + (wn << 5);
    float2 bv[4];
    #pragma unroll
    for (int nf = 0; nf < 4; nf++)
        bv[nf] = *(const float2*)(bias + cbase + (nf << 3) + ((lane & 3) << 1));
    #pragma unroll
    for (int mf = 0; mf < 4; mf++)
        #pragma unroll
        for (int nf = 0; nf < 4; nf++) {
            acc[mf][nf][0] += bv[nf].x; acc[mf][nf][1] += bv[nf].y;
            acc[mf][nf][2] += bv[nf].x; acc[mf][nf][3] += bv[nf].y;
        }

    if (MODE == 1) {
        // row softmax over the 64-col head (this warp + partner wn^1), *SCALE.
        float* sred = (float*)sm;        // [wm*4+wn][2][64] floats = 4KB
        const int me = (wm << 2) + wn, pr = (wm << 2) + (wn ^ 1);
        #pragma unroll
        for (int mf = 0; mf < 4; mf++)
            #pragma unroll
            for (int half = 0; half < 2; half++) {
                float mx = acc[mf][0][half * 2];
                #pragma unroll
                for (int nf = 0; nf < 4; nf++) {
                    mx = fmaxf(mx, acc[mf][nf][half * 2]);
                    mx = fmaxf(mx, acc[mf][nf][half * 2 + 1]);
                }
                mx = fmaxf(mx, __shfl_xor_sync(0xffffffffu, mx, 1));
                mx = fmaxf(mx, __shfl_xor_sync(0xffffffffu, mx, 2));
                if ((lane & 3) == 0)
                    sred[(me * 2 + 0) * 64 + (mf << 4) + (lane >> 2) + half * 8] = mx;
            }
        __syncthreads();
        #pragma unroll
        for (int mf = 0; mf < 4; mf++)
            #pragma unroll
            for (int half = 0; half < 2; half++) {
                const int row = (mf << 4) + (lane >> 2) + half * 8;
                const float m = fmaxf(sred[(me * 2 + 0) * 64 + row],
                                      sred[(pr * 2 + 0) * 64 + row]);
                float s = 0.f;
                #pragma unroll
                for (int nf = 0; nf < 4; nf++) {
                    acc[mf][nf][half * 2]     = __expf(acc[mf][nf][half * 2]     - m);
                    acc[mf][nf][half * 2 + 1] = __expf(acc[mf][nf][half * 2 + 1] - m);
                    s += acc[mf][nf][half * 2] + acc[mf][nf][half * 2 + 1];
                }
                s += __shfl_xor_sync(0xffffffffu, s, 1);
                s += __shfl_xor_sync(0xffffffffu, s, 2);
                if ((lane & 3) == 0) sred[(me * 2 + 1) * 64 + row] = s;
            }
        __syncthreads();
        #pragma unroll
        for (int mf = 0; mf < 4; mf++)
            #pragma unroll
            for (int half = 0; half < 2; half++) {
                const int row = (mf << 4) + (lane >> 2) + half * 8;
                const float s = sred[(me * 2 + 1) * 64 + row] +
                                sred[(pr * 2 + 1) * 64 + row];
                const float inv = SCALE / s;
                #pragma unroll
                for (int nf = 0; nf < 4; nf++) {
                    acc[mf][nf][half * 2]     *= inv;
                    acc[mf][nf][half * 2 + 1] *= inv;
                }
            }
    }

    #pragma unroll
    for (int mf = 0; mf < 4; mf++) {
        const int r0 = m0 + (wm << 6) + (mf << 4) + (lane >> 2);
        #pragma unroll
        for (int nf = 0; nf < 4; nf++) {
            const int co = (nf << 3) + ((lane & 3) << 1);
            if (MODE == 0) {
                float* Cp = C + (long long)r0 * DD + cbase + co;
                *(float2*)Cp             = make_float2(acc[mf][nf][0], acc[mf][nf][1]);
                *(float2*)(Cp + 8LL*DD)  = make_float2(acc[mf][nf][2], acc[mf][nf][3]);
            } else {
                const int w = (cbase >> 1) + (nf << 2) + (lane & 3);
                Cb[(size_t)r0 * DW + w]       = pack2(acc[mf][nf][0], acc[mf][nf][1]);
                Cb[(size_t)(r0 + 8) * DW + w] = pack2(acc[mf][nf][2], acc[mf][nf][3]);
            }
        }
    }
}

// ---------------------------------------------------------------------------
// pack_w: W[k][n] -> Wtb[n][k/2] packed bf16 (transpose + pack)
// ---------------------------------------------------------------------------
__global__ void __launch_bounds__(256) pack_w(const float* __restrict__ W,
                                              uint32_t* __restrict__ Wtb)
{
    __shared__ float s[64][36];
    const int n0 = blockIdx.x << 5, k0 = blockIdx.y << 6;
    const int tid = threadIdx.x;
    {
        const int i = tid >> 2, j8 = (tid & 3) << 3;
        *(float4*)&s[i][j8]     = *(const float4*)(W + (size_t)(k0 + i) * DD + n0 + j8);
        *(float4*)&s[i][j8 + 4] = *(const float4*)(W + (size_t)(k0 + i) * DD + n0 + j8 + 4);
    }
    __syncthreads();
    const int nl = tid >> 3, kg = tid & 7;
    uint4 o;
    o.x = pack2(s[kg * 8 + 0][nl], s[kg * 8 + 1][nl]);
    o.y = pack2(s[kg * 8 + 2][nl], s[kg * 8 + 3][nl]);
    o.z = pack2(s[kg * 8 + 4][nl], s[kg * 8 + 5][nl]);
    o.w = pack2(s[kg * 8 + 6][nl], s[kg * 8 + 7][nl]);
    *(uint4*)(Wtb + (size_t)(n0 + nl) * DW + (k0 >> 1) + (kg << 2)) = o;
}

// ---------------------------------------------------------------------------
// pack_rows: fp32 row-major -> packed bf16
// ---------------------------------------------------------------------------
__global__ void __launch_bounds__(256) pack_rows(const float* __restrict__ src,
                                                 uint32_t* __restrict__ dst)
{
    const size_t q = ((size_t)blockIdx.x * 256 + threadIdx.x) << 3;
    float4 a = *(const float4*)(src + q), b = *(const float4*)(src + q + 4);
    uint4 o = {pack2(a.x, a.y), pack2(a.z, a.w), pack2(b.x, b.y), pack2(b.z, b.w)};
    *(uint4*)(dst + (q >> 1)) = o;
}

// ---------------------------------------------------------------------------
// Column softmax over seq dim N, reading packed bf16 Qb (the same operand the
// final GEMM consumes) -> packed bf16 g_KmB.  32 cols (16 words) per CTA.
// Values bounded in [0, SCALE] -> no max pass needed (2 passes).
// ---------------------------------------------------------------------------
__global__ void __launch_bounds__(512) col_softmax()
{
    const int b  = blockIdx.y;
    const int w0 = blockIdx.x << 4;           // first word of 16
    const int tx = threadIdx.x & 7;           // 8 word-pairs
    const int ty = threadIdx.x >> 3;          // 64 row strides
    const uint32_t* src = g_Qb  + (size_t)b * NN * DW + w0 + (tx << 1);
    uint32_t*       dst = g_KmB + (size_t)b * NN * DW + w0 + (tx << 1);

    __shared__ float4 red[64][8];

    float4 s4 = {0.f, 0.f, 0.f, 0.f};
    for (int n = ty; n < NN; n += 64) {
        uint2 w = *(const uint2*)(src + (size_t)n * DW);
        s4.x += __expf(bf_lo(w.x)); s4.y += __expf(bf_hi(w.x));
        s4.z += __expf(bf_lo(w.y)); s4.w += __expf(bf_hi(w.y));
    }
    red[ty][tx] = s4;
    __syncthreads();
    s4.x = 0.f; s4.y = 0.f; s4.z = 0.f; s4.w = 0.f;
    #pragma unroll 8
    for (int i = 0; i < 64; i++) {
        float4 r = red[i][tx];
        s4.x += r.x; s4.y += r.y; s4.z += r.z; s4.w += r.w;
    }
    const float4 inv = {SCALE / s4.x, SCALE / s4.y, SCALE / s4.z, SCALE / s4.w};

    for (int n = ty; n < NN; n += 64) {
        uint2 w = *(const uint2*)(src + (size_t)n * DW);
        uint2 o;
        o.x = pack2(__expf(bf_lo(w.x)) * inv.x, __expf(bf_hi(w.x)) * inv.y);
        o.y = pack2(__expf(bf_lo(w.y)) * inv.z, __expf(bf_hi(w.y)) * inv.w);
        *(uint2*)(dst + (size_t)n * DW) = o;
    }
}

// ---------------------------------------------------------------------------
// ctx via tensor cores: ctx[sp][bh][d][e] = sum_{n in slice} Km[n,d]*V[n,e]
// CTXSP=4 splits (1024 rows each) -> 256 CTAs, 2 balanced waves on 148 SMs.
// ---------------------------------------------------------------------------
__global__ void __launch_bounds__(256) ctx_mma()
{
    __shared__ uint32_t cs[4][2048];   // 32KB: per stage [Km 1024w | V 1024w]
    const int bh = blockIdx.x, b = bh >> 4, h = bh & 15;
    const int n0 = blockIdx.y << 10;   // 1024 rows per split
    const int tid = threadIdx.x, lane = tid & 31, wid = tid >> 5;
    const int wd = wid >> 1, we = wid & 1;
    const uint32_t sbase = smem_u32(cs);

    const uint32_t* KmP = g_KmB + (size_t)b * NN * DW + h * 32;
    const uint32_t* VbP = g_Vb  + (size_t)b * NN * DW + h * 32;

    const int lop = tid >> 7, t7 = tid & 127;
    const int lrow = t7 >> 2, lc2 = (t7 & 3) << 1;
    const uint32_t* lsrc = (lop ? VbP : KmP) + (size_t)(n0 + lrow) * DW;
    const uint32_t d0 = sbase + (((lop << 10) + lrow * 32 + ((lc2       ^ (lrow & 7)) << 2)) << 2);
    const uint32_t d1 = sbase + (((lop << 10) + lrow * 32 + (((lc2 + 1) ^ (lrow & 7)) << 2)) << 2);

    auto issue = [&](int t) {
        const uint32_t so = (uint32_t)(t & 3) << 13;
        const uint32_t* s = lsrc + (size_t)(t << 5) * DW;
        CP_ASYNC16(d0 + so, s + (lc2 << 2));
        CP_ASYNC16(d1 + so, s + ((lc2 + 1) << 2));
    };

    const int arow = (lane & 7) | ((lane & 16) >> 1);
    const int achk = (wd << 1) + ((lane >> 3) & 1);
    const int brow = lane & 15;

    float acc[4][4];
    #pragma unroll
    for (int i = 0; i < 4; i++)
        #pragma unroll
        for (int j = 0; j < 4; j++) acc[i][j] = 0.f;

    auto compute = [&](int stg) {
        const uint32_t so = (uint32_t)stg << 13;
        #pragma unroll
        for (int ks = 0; ks < 2; ks++) {
            uint32_t af[4], bg[2][4];
            {
                const int r = (ks << 4) + arow;
                LDM_X4T(af, sbase + so + ((r * 32 + ((achk ^ (r & 7)) << 2)) << 2));
            }
            #pragma unroll
            for (int np = 0; np < 2; np++) {
                const int r = (ks << 4) + brow;
                const int c = (we << 2) + (np << 1) + (lane >> 4);
                LDM_X4T(bg[np], sbase + so + ((1024 + r * 32 + ((c ^ (r & 7)) << 2)) << 2));
            }
            #pragma unroll
            for (int nf = 0; nf < 4; nf++)
                MMA_BF16(acc[nf], af,
                         bg[nf >> 1][(nf & 1) << 1], bg[nf >> 1][((nf & 1) << 1) + 1]);
        }
    };

    issue(0); CP_COMMIT();
    issue(1); CP_COMMIT();
    issue(2); CP_COMMIT();
    for (int t = 0; t < 32; t++) {
        CP_WAIT2();
        __syncthreads();
        compute(t & 3);
        if (t + 3 < 32) issue(t + 3);
        CP_COMMIT();
    }

    float* o = g_ctx + (((size_t)blockIdx.y * (BB * HH) + bh) << 12);
    const int d = (wd << 4) + (lane >> 2);
    #pragma unroll
    for (int nf = 0; nf < 4; nf++) {
        const int e = (we << 5) + (nf << 3) + ((lane & 3) << 1);
        *(float2*)(o + d * 64 + e)       = make_float2(acc[nf][0], acc[nf][1]);
        *(float2*)(o + (d + 8) * 64 + e) = make_float2(acc[nf][2], acc[nf][3]);
    }
}

// ---------------------------------------------------------------------------
// Mbig^T packed: g_Mtb[b][n][k/2] = pack(sum_e ctx[b,h][d][e]*Wo[h*64+e][n])
// ---------------------------------------------------------------------------
__global__ void __launch_bounds__(256) mbig_kernel(const float* __restrict__ Wo)
{
    const int bh = blockIdx.x, b = bh >> 4, h = bh & 15;
    const int c0 = blockIdx.y << 6;

    __shared__ float csx[64][64];
    __shared__ float ws[64][64];
    const int tid = threadIdx.x;

    for (int i = tid; i < 4096; i += 256) {
        float sum = 0.f;
        #pragma unroll
        for (int sp = 0; sp < CTXSP; sp++)
            sum += g_ctx[(((size_t)sp * (BB * HH) + bh) << 12) + i];
        csx[i >> 6][i & 63] = sum;
    }
    for (int i = tid; i < 1024; i += 256) {
        int rr = i >> 4, cc = (i & 15) << 2;
        *(float4*)&ws[rr][cc] =
            *(const float4*)(Wo + (size_t)(h * DH + rr) * DD + c0 + cc);
    }
    __syncthreads();

    const int r0 = (tid >> 4) << 2, cc0 = (tid & 15) << 2;
    float acc[4][4] = {};
    #pragma unroll 16
    for (int k = 0; k < 64; k++) {
        float a[4], w[4];
        #pragma unroll
        for (int i = 0; i < 4; i++) a[i] = csx[r0 + i][k];
        *(float4*)w = *(float4*)&ws[k][cc0];
        #pragma unroll
        for (int i = 0; i < 4; i++)
            #pragma unroll
            for (int j = 0; j < 4; j++)
                acc[i][j] = fmaf(a[i], w[j], acc[i][j]);
    }
    uint32_t* ob = g_Mtb + ((size_t)b * DD * DW);
    const int kb2 = (h * DH + r0) >> 1;
    #pragma unroll
    for (int j = 0; j < 4; j++) {
        const size_t n = (size_t)(c0 + cc0 + j);
        ob[n * DW + kb2]     = pack2(acc[0][j], acc[1][j]);
        ob[n * DW + kb2 + 1] = pack2(acc[2][j], acc[3][j]);
    }
}

// ---------------------------------------------------------------------------
// Launcher. Inputs: 0:x 1:Wq 2:bq 3:Wk(dead) 4:bk(dead) 5:Wv 6:bv 7:Wo 8:bo
// ---------------------------------------------------------------------------
extern "C" void kernel_launch(void* const* d_in, const int* in_sizes, int n_in,
                              void* d_out, int out_size)
{
    const float* x  = (const float*)d_in[0];
    const float* Wq = (const float*)d_in[1];
    const float* bq = (const float*)d_in[2];
    const float* Wv = (const float*)d_in[5];
    const float* bv = (const float*)d_in[6];
    const float* Wo = (const float*)d_in[7];
    const float* bo = (const float*)d_in[8];
    float* out = (float*)d_out;

    uint32_t *xb, *Qb, *Vb, *Wqb, *Wvb, *Mtb;
    cudaGetSymbolAddress((void**)&xb,  g_xb);
    cudaGetSymbolAddress((void**)&Qb,  g_Qb);
    cudaGetSymbolAddress((void**)&Vb,  g_Vb);
    cudaGetSymbolAddress((void**)&Wqb, g_Wqb);
    cudaGetSymbolAddress((void**)&Wvb, g_Wvb);
    cudaGetSymbolAddress((void**)&Mtb, g_Mtb);

    cudaFuncSetAttribute((const void*)gemm_bf16<0>,
                         cudaFuncAttributeMaxDynamicSharedMemorySize, GEMM_SMEM);
    cudaFuncSetAttribute((const void*)gemm_bf16<1>,
                         cudaFuncAttributeMaxDynamicSharedMemorySize, GEMM_SMEM);
    cudaFuncSetAttribute((const void*)gemm_bf16<2>,
                         cudaFuncAttributeMaxDynamicSharedMemorySize, GEMM_SMEM);

    const long long sXW = (long long)NN * DW;
    const long long sXD = (long long)NN * DD;
    dim3 ggrid(DD / 128, NN / 128, BB);

    pack_rows<<<(BB * NN * DD) / (256 * 8), 256>>>(x, xb);
    pack_w<<<dim3(DD / 32, DD / 64), 256>>>(Wq, Wqb);
    pack_w<<<dim3(DD / 32, DD / 64), 256>>>(Wv, Wvb);

    // Q = softmax(x@Wq + bq) * s  (fused epilogue; packed bf16 only)
    gemm_bf16<1><<<ggrid, 256, GEMM_SMEM>>>(xb, Wqb, bq, out, Qb, sXW, 0, sXD);
    // V = x@Wv + bv  (packed bf16 only)
    gemm_bf16<2><<<ggrid, 256, GEMM_SMEM>>>(xb, Wvb, bv, out, Vb, sXW, 0, sXD);

    // Km = softmax(Qb, seq) * s  (packed bf16; 2-pass, bounded values)
    col_softmax<<<dim3(DD / 32, BB), 512>>>();

    // ctx partials (tensor cores), then Mbig^T packed
    ctx_mma<<<dim3(BB * HH, CTXSP), 256>>>();
    mbig_kernel<<<dim3(BB * HH, DD / 64), 256>>>(Wo);

    // out[b] = Qs[b] @ Mbig[b] + bo
    gemm_bf16<0><<<ggrid, 256, GEMM_SMEM>>>(Qb, Mtb, bo, out, Qb,
                                            sXW, (long long)DD * DW, sXD);
}

// round 15
// speedup vs baseline: 1.5421x; 1.0030x over previous
#include <cuda_runtime.h>
#include <cstdint>

// Shapes fixed: B=4, N=4096, D=1024, H=16, d_head=64.
#define BB 4
#define NN 4096
#define DD 1024
#define DW 512            // packed bf16x2 words per row of 1024
#define HH 16
#define DH 64
#define CTXSP 4
#define SCALE 0.5946035575013605f   // (d_head^0.5)^(-0.25) = 2^(-0.75)

// Scratch (__device__ globals; no cudaMalloc allowed).
__device__ float    g_ctx[(size_t)CTXSP * BB * HH * DH * DH];
__device__ uint32_t g_xb  [(size_t)BB * NN * DW];  // x packed bf16
__device__ uint32_t g_Qb  [(size_t)BB * NN * DW];  // softmaxed Q packed bf16
__device__ uint32_t g_Vb  [(size_t)BB * NN * DW];  // V proj packed bf16
__device__ uint32_t g_KmB [(size_t)BB * NN * DW];  // column-softmax packed bf16
__device__ uint32_t g_Wqvb[(size_t)2 * DD * DW];   // [Wq^T ; Wv^T] packed bf16
__device__ uint32_t g_Mtb [(size_t)BB * DD * DW];  // Mbig^T packed bf16

// ---------------------------------------------------------------------------
// helpers
// ---------------------------------------------------------------------------
__device__ __forceinline__ uint32_t smem_u32(const void* p) {
    uint32_t a;
    asm("{ .reg .u64 t; cvta.to.shared.u64 t, %1; cvt.u32.u64 %0, t; }" : "=r"(a) : "l"(p));
    return a;
}
__device__ __forceinline__ uint32_t pack2(float lo, float hi) {
    uint32_t r;
    asm("cvt.rn.bf16x2.f32 %0, %1, %2;" : "=r"(r) : "f"(hi), "f"(lo));
    return r;
}
__device__ __forceinline__ float bf_lo(uint32_t w) { return __uint_as_float(w << 16); }
__device__ __forceinline__ float bf_hi(uint32_t w) { return __uint_as_float(w & 0xffff0000u); }

#define CP_ASYNC16(dst, src) \
    asm volatile("cp.async.cg.shared.global [%0], [%1], 16;" :: "r"(dst), "l"(src) : "memory")
#define CP_COMMIT()  asm volatile("cp.async.commit_group;" ::: "memory")
#define CP_WAIT2()   asm volatile("cp.async.wait_group 2;" ::: "memory")

#define LDM_X4(r, a)                                                            \
    asm volatile("ldmatrix.sync.aligned.m8n8.x4.shared.b16 {%0,%1,%2,%3}, [%4];"\
        : "=r"((r)[0]), "=r"((r)[1]), "=r"((r)[2]), "=r"((r)[3]) : "r"(a))
#define LDM_X4T(r, a)                                                           \
    asm volatile("ldmatrix.sync.aligned.m8n8.x4.trans.shared.b16 {%0,%1,%2,%3}, [%4];"\
        : "=r"((r)[0]), "=r"((r)[1]), "=r"((r)[2]), "=r"((r)[3]) : "r"(a))
#define MMA_BF16(d, a, b0, b1)                                                  \
    asm volatile("mma.sync.aligned.m16n8k16.row.col.f32.bf16.bf16.f32 "         \
        "{%0,%1,%2,%3}, {%4,%5,%6,%7}, {%8,%9}, {%0,%1,%2,%3};"                 \
        : "+f"((d)[0]), "+f"((d)[1]), "+f"((d)[2]), "+f"((d)[3])                \
        : "r"((a)[0]), "r"((a)[1]), "r"((a)[2]), "r"((a)[3]), "r"(b0), "r"(b1))

#define GEMM_SMEM 65536

// ---------------------------------------------------------------------------
// Merged Q+V projection GEMM.  n spans 2048: [0,1024) = Q (row-softmax
// epilogue -> Qb), [1024,2048) = V (bias only -> Vb).  A = xb shared.
// Mainloop identical to the verified R10/R12 kernel (CTA 128x128, 8 warps
// 2x4, K-chunk 32, 4-stage cp.async ring, 2 CTAs/SM).
// ---------------------------------------------------------------------------
__global__ void __launch_bounds__(256, 2)
gemm_qv(const uint32_t* __restrict__ A, const uint32_t* __restrict__ Bt,
        const float* __restrict__ bq, const float* __restrict__ bv,
        uint32_t* __restrict__ Qb, uint32_t* __restrict__ Vb)
{
    extern __shared__ uint32_t sm[];

    const int b = blockIdx.z;
    A += (long long)b * NN * DW;
    const int n0 = blockIdx.x << 7;     // 0..2047
    const int m0 = blockIdx.y << 7;
    const int tid = threadIdx.x, lane = tid & 31, wid = tid >> 5;
    const int wm = wid >> 2, wn = wid & 3;

    const uint32_t sbase = smem_u32(sm);

    const int lr  = tid >> 1;
    const int lk8 = (tid & 1) << 3;
    const uint32_t* Ap = A  + (long long)(m0 + lr) * DW + lk8;
    const uint32_t* Bp = Bt + (long long)(n0 + lr) * DW + lk8;
    const int lswz = (lr >> 1) & 3;
    const int cb   = lk8 >> 2;
    const uint32_t stA0 = sbase + (lr << 6) + ((cb ^ lswz) << 4);
    const uint32_t stA1 = sbase + (lr << 6) + (((cb + 1) ^ lswz) << 4);

    auto issue = [&](int t) {
        const uint32_t so = (uint32_t)(t & 3) << 14;
        const uint32_t* a  = Ap + (t << 4);
        const uint32_t* bb = Bp + (t << 4);
        CP_ASYNC16(stA0 + so,         a);
        CP_ASYNC16(stA1 + so,         a + 4);
        CP_ASYNC16(stA0 + so + 8192u, bb);
        CP_ASYNC16(stA1 + so + 8192u, bb + 4);
    };

    const int ar16 = lane & 15;
    const int acs  = lane >> 4;
    const int aswz = (ar16 >> 1) & 3;
    const int br16 = (lane & 7) | ((lane & 16) >> 1);
    const int bcs  = (lane >> 3) & 1;
    const int bswz = (br16 >> 1) & 3;

    float acc[4][4][4];
    #pragma unroll
    for (int i = 0; i < 4; i++)
        #pragma unroll
        for (int j = 0; j < 4; j++)
            #pragma unroll
            for (int r = 0; r < 4; r++) acc[i][j][r] = 0.f;

    auto compute = [&](int stg) {
        const uint32_t so = (uint32_t)stg << 14;
        const uint32_t abase = sbase + so + (((wm << 6) + ar16) << 6);
        const uint32_t bbase = sbase + so + 8192u + (((wn << 5) + br16) << 6);
        #pragma unroll
        for (int ks = 0; ks < 2; ks++) {
            uint32_t af[4][4], bg[2][4];
            const uint32_t ac = (uint32_t)((((ks << 1) + acs) ^ aswz) << 4);
            const uint32_t bc = (uint32_t)((((ks << 1) + bcs) ^ bswz) << 4);
            #pragma unroll
            for (int mf = 0; mf < 4; mf++)
                LDM_X4(af[mf], abase + (uint32_t)(mf << 10) + ac);
            #pragma unroll
            for (int np = 0; np < 2; np++)
                LDM_X4(bg[np], bbase + (uint32_t)(np << 10) + bc);
            #pragma unroll
            for (int mf = 0; mf < 4; mf++)
                #pragma unroll
                for (int nf = 0; nf < 4; nf++)
                    MMA_BF16(acc[mf][nf], af[mf],
                             bg[nf >> 1][(nf & 1) << 1], bg[nf >> 1][((nf & 1) << 1) + 1]);
        }
    };

    issue(0); CP_COMMIT();
    issue(1); CP_COMMIT();
    issue(2); CP_COMMIT();
    for (int t = 0; t < 32; t++) {
        CP_WAIT2();
        __syncthreads();
        compute(t & 3);
        if (t + 3 < 32) issue(t + 3);
        CP_COMMIT();
    }

    // ---- epilogue (CTA-uniform Q/V select) ---------------------------------
    const bool isV = n0 >= 1024;
    const float* bias = isV ? (bv - 1024) : bq;
    const int cbase = n0 + (wn << 5);

    float2 bvv[4];
    #pragma unroll
    for (int nf = 0; nf < 4; nf++)
        bvv[nf] = *(const float2*)(bias + cbase + (nf << 3) + ((lane & 3) << 1));
    #pragma unroll
    for (int mf = 0; mf < 4; mf++)
        #pragma unroll
        for (int nf = 0; nf < 4; nf++) {
            acc[mf][nf][0] += bvv[nf].x; acc[mf][nf][1] += bvv[nf].y;
            acc[mf][nf][2] += bvv[nf].x; acc[mf][nf][3] += bvv[nf].y;
        }

    if (!isV) {
        // row softmax over the 64-col head (this warp + partner wn^1), *SCALE.
        float* sred = (float*)sm;        // [wm*4+wn][2][64] floats = 4KB
        const int me = (wm << 2) + wn, pr = (wm << 2) + (wn ^ 1);
        #pragma unroll
        for (int mf = 0; mf < 4; mf++)
            #pragma unroll
            for (int half = 0; half < 2; half++) {
                float mx = acc[mf][0][half * 2];
                #pragma unroll
                for (int nf = 0; nf < 4; nf++) {
                    mx = fmaxf(mx, acc[mf][nf][half * 2]);
                    mx = fmaxf(mx, acc[mf][nf][half * 2 + 1]);
                }
                mx = fmaxf(mx, __shfl_xor_sync(0xffffffffu, mx, 1));
                mx = fmaxf(mx, __shfl_xor_sync(0xffffffffu, mx, 2));
                if ((lane & 3) == 0)
                    sred[(me * 2 + 0) * 64 + (mf << 4) + (lane >> 2) + half * 8] = mx;
            }
        __syncthreads();
        #pragma unroll
        for (int mf = 0; mf < 4; mf++)
            #pragma unroll
            for (int half = 0; half < 2; half++) {
                const int row = (mf << 4) + (lane >> 2) + half * 8;
                const float m = fmaxf(sred[(me * 2 + 0) * 64 + row],
                                      sred[(pr * 2 + 0) * 64 + row]);
                float s = 0.f;
                #pragma unroll
                for (int nf = 0; nf < 4; nf++) {
                    acc[mf][nf][half * 2]     = __expf(acc[mf][nf][half * 2]     - m);
                    acc[mf][nf][half * 2 + 1] = __expf(acc[mf][nf][half * 2 + 1] - m);
                    s += acc[mf][nf][half * 2] + acc[mf][nf][half * 2 + 1];
                }
                s += __shfl_xor_sync(0xffffffffu, s, 1);
                s += __shfl_xor_sync(0xffffffffu, s, 2);
                if ((lane & 3) == 0) sred[(me * 2 + 1) * 64 + row] = s;
            }
        __syncthreads();
        #pragma unroll
        for (int mf = 0; mf < 4; mf++)
            #pragma unroll
            for (int half = 0; half < 2; half++) {
                const int row = (mf << 4) + (lane >> 2) + half * 8;
                const float s = sred[(me * 2 + 1) * 64 + row] +
                                sred[(pr * 2 + 1) * 64 + row];
                const float inv = SCALE / s;
                #pragma unroll
                for (int nf = 0; nf < 4; nf++) {
                    acc[mf][nf][half * 2]     *= inv;
                    acc[mf][nf][half * 2 + 1] *= inv;
                }
            }
    }

    uint32_t* Cb = (isV ? g_Vb : g_Qb) + (size_t)b * NN * DW;
    const int wbase = (cbase >> 1) - (isV ? 512 : 0);
    #pragma unroll
    for (int mf = 0; mf < 4; mf++) {
        const int r0 = m0 + (wm << 6) + (mf << 4) + (lane >> 2);
        #pragma unroll
        for (int nf = 0; nf < 4; nf++) {
            const int w = wbase + (nf << 2) + (lane & 3);
            Cb[(size_t)r0 * DW + w]       = pack2(acc[mf][nf][0], acc[mf][nf][1]);
            Cb[(size_t)(r0 + 8) * DW + w] = pack2(acc[mf][nf][2], acc[mf][nf][3]);
        }
    }
}

// ---------------------------------------------------------------------------
// Final GEMM: out[b] = Qb[b] @ Mtb[b]^T + bo  (fp32 out).  R10-verified.
// ---------------------------------------------------------------------------
__global__ void __launch_bounds__(256, 2)
gemm_out(const uint32_t* __restrict__ A, const uint32_t* __restrict__ Bt,
         const float* __restrict__ bias, float* __restrict__ C)
{
    extern __shared__ uint32_t sm[];

    const int b = blockIdx.z;
    A  += (long long)b * NN * DW;
    Bt += (long long)b * DD * DW;
    C  += (long long)b * NN * DD;
    const int n0 = blockIdx.x << 7;
    const int m0 = blockIdx.y << 7;
    const int tid = threadIdx.x, lane = tid & 31, wid = tid >> 5;
    const int wm = wid >> 2, wn = wid & 3;

    const uint32_t sbase = smem_u32(sm);

    const int lr  = tid >> 1;
    const int lk8 = (tid & 1) << 3;
    const uint32_t* Ap = A  + (long long)(m0 + lr) * DW + lk8;
    const uint32_t* Bp = Bt + (long long)(n0 + lr) * DW + lk8;
    const int lswz = (lr >> 1) & 3;
    const int cb   = lk8 >> 2;
    const uint32_t stA0 = sbase + (lr << 6) + ((cb ^ lswz) << 4);
    const uint32_t stA1 = sbase + (lr << 6) + (((cb + 1) ^ lswz) << 4);

    auto issue = [&](int t) {
        const uint32_t so = (uint32_t)(t & 3) << 14;
        const uint32_t* a  = Ap + (t << 4);
        const uint32_t* bb = Bp + (t << 4);
        CP_ASYNC16(stA0 + so,         a);
        CP_ASYNC16(stA1 + so,         a + 4);
        CP_ASYNC16(stA0 + so + 8192u, bb);
        CP_ASYNC16(stA1 + so + 8192u, bb + 4);
    };

    const int ar16 = lane & 15;
    const int acs  = lane >> 4;
    const int aswz = (ar16 >> 1) & 3;
    const int br16 = (lane & 7) | ((lane & 16) >> 1);
    const int bcs  = (lane >> 3) & 1;
    const int bswz = (br16 >> 1) & 3;

    float acc[4][4][4];
    #pragma unroll
    for (int i = 0; i < 4; i++)
        #pragma unroll
        for (int j = 0; j < 4; j++)
            #pragma unroll
            for (int r = 0; r < 4; r++) acc[i][j][r] = 0.f;

    auto compute = [&](int stg) {
        const uint32_t so = (uint32_t)stg << 14;
        const uint32_t abase = sbase + so + (((wm << 6) + ar16) << 6);
        const uint32_t bbase = sbase + so + 8192u + (((wn << 5) + br16) << 6);
        #pragma unroll
        for (int ks = 0; ks < 2; ks++) {
            uint32_t af[4][4], bg[2][4];
            const uint32_t ac = (uint32_t)((((ks << 1) + acs) ^ aswz) << 4);
            const uint32_t bc = (uint32_t)((((ks << 1) + bcs) ^ bswz) << 4);
            #pragma unroll
            for (int mf = 0; mf < 4; mf++)
                LDM_X4(af[mf], abase + (uint32_t)(mf << 10) + ac);
            #pragma unroll
            for (int np = 0; np < 2; np++)
                LDM_X4(bg[np], bbase + (uint32_t)(np << 10) + bc);
            #pragma unroll
            for (int mf = 0; mf < 4; mf++)
                #pragma unroll
                for (int nf = 0; nf < 4; nf++)
                    MMA_BF16(acc[mf][nf], af[mf],
                             bg[nf >> 1][(nf & 1) << 1], bg[nf >> 1][((nf & 1) << 1) + 1]);
        }
    };

    issue(0); CP_COMMIT();
    issue(1); CP_COMMIT();
    issue(2); CP_COMMIT();
    for (int t = 0; t < 32; t++) {
        CP_WAIT2();
        __syncthreads();
        compute(t & 3);
        if (t + 3 < 32) issue(t + 3);
        CP_COMMIT();
    }

    const int cbase = n0 + (wn << 5);
    float2 bv[4];
    #pragma unroll
    for (int nf = 0; nf < 4; nf++)
        bv[nf] = *(const float2*)(bias + cbase + (nf << 3) + ((lane & 3) << 1));

    #pragma unroll
    for (int mf = 0; mf < 4; mf++) {
        const int r0 = m0 + (wm << 6) + (mf << 4) + (lane >> 2);
        #pragma unroll
        for (int nf = 0; nf < 4; nf++) {
            const int co = (nf << 3) + ((lane & 3) << 1);
            float* Cp = C + (long long)r0 * DD + cbase + co;
            *(float2*)Cp            = make_float2(acc[mf][nf][0] + bv[nf].x,
                                                  acc[mf][nf][1] + bv[nf].y);
            *(float2*)(Cp + 8LL*DD) = make_float2(acc[mf][nf][2] + bv[nf].x,
                                                  acc[mf][nf][3] + bv[nf].y);
        }
    }
}

// ---------------------------------------------------------------------------
// pack_w: W[k][n] -> Wtb[n][k/2] packed bf16 (transpose + pack)
// ---------------------------------------------------------------------------
__global__ void __launch_bounds__(256) pack_w(const float* __restrict__ W,
                                              uint32_t* __restrict__ Wtb)
{
    __shared__ float s[64][36];
    const int n0 = blockIdx.x << 5, k0 = blockIdx.y << 6;
    const int tid = threadIdx.x;
    {
        const int i = tid >> 2, j8 = (tid & 3) << 3;
        *(float4*)&s[i][j8]     = *(const float4*)(W + (size_t)(k0 + i) * DD + n0 + j8);
        *(float4*)&s[i][j8 + 4] = *(const float4*)(W + (size_t)(k0 + i) * DD + n0 + j8 + 4);
    }
    __syncthreads();
    const int nl = tid >> 3, kg = tid & 7;
    uint4 o;
    o.x = pack2(s[kg * 8 + 0][nl], s[kg * 8 + 1][nl]);
    o.y = pack2(s[kg * 8 + 2][nl], s[kg * 8 + 3][nl]);
    o.z = pack2(s[kg * 8 + 4][nl], s[kg * 8 + 5][nl]);
    o.w = pack2(s[kg * 8 + 6][nl], s[kg * 8 + 7][nl]);
    *(uint4*)(Wtb + (size_t)(n0 + nl) * DW + (k0 >> 1) + (kg << 2)) = o;
}

// ---------------------------------------------------------------------------
// pack_rows: fp32 row-major -> packed bf16
// ---------------------------------------------------------------------------
__global__ void __launch_bounds__(256) pack_rows(const float* __restrict__ src,
                                                 uint32_t* __restrict__ dst)
{
    const size_t q = ((size_t)blockIdx.x * 256 + threadIdx.x) << 3;
    float4 a = *(const float4*)(src + q), b = *(const float4*)(src + q + 4);
    uint4 o = {pack2(a.x, a.y), pack2(a.z, a.w), pack2(b.x, b.y), pack2(b.z, b.w)};
    *(uint4*)(dst + (q >> 1)) = o;
}

// ---------------------------------------------------------------------------
// Column softmax over seq dim N from packed bf16 Qb -> packed bf16 g_KmB.
// 32 cols (16 words) per CTA.  Values bounded in [0, SCALE] -> 2 passes.
// ---------------------------------------------------------------------------
__global__ void __launch_bounds__(512) col_softmax()
{
    const int b  = blockIdx.y;
    const int w0 = blockIdx.x << 4;
    const int tx = threadIdx.x & 7;
    const int ty = threadIdx.x >> 3;
    const uint32_t* src = g_Qb  + (size_t)b * NN * DW + w0 + (tx << 1);
    uint32_t*       dst = g_KmB + (size_t)b * NN * DW + w0 + (tx << 1);

    __shared__ float4 red[64][8];

    float4 s4 = {0.f, 0.f, 0.f, 0.f};
    for (int n = ty; n < NN; n += 64) {
        uint2 w = *(const uint2*)(src + (size_t)n * DW);
        s4.x += __expf(bf_lo(w.x)); s4.y += __expf(bf_hi(w.x));
        s4.z += __expf(bf_lo(w.y)); s4.w += __expf(bf_hi(w.y));
    }
    red[ty][tx] = s4;
    __syncthreads();
    s4.x = 0.f; s4.y = 0.f; s4.z = 0.f; s4.w = 0.f;
    #pragma unroll 8
    for (int i = 0; i < 64; i++) {
        float4 r = red[i][tx];
        s4.x += r.x; s4.y += r.y; s4.z += r.z; s4.w += r.w;
    }
    const float4 inv = {SCALE / s4.x, SCALE / s4.y, SCALE / s4.z, SCALE / s4.w};

    for (int n = ty; n < NN; n += 64) {
        uint2 w = *(const uint2*)(src + (size_t)n * DW);
        uint2 o;
        o.x = pack2(__expf(bf_lo(w.x)) * inv.x, __expf(bf_hi(w.x)) * inv.y);
        o.y = pack2(__expf(bf_lo(w.y)) * inv.z, __expf(bf_hi(w.y)) * inv.w);
        *(uint2*)(dst + (size_t)n * DW) = o;
    }
}

// ---------------------------------------------------------------------------
// ctx via tensor cores: ctx[sp][bh][d][e] = sum_{n in slice} Km[n,d]*V[n,e]
// CTXSP=4 splits -> 256 CTAs, 2 balanced waves on 148 SMs.
// ---------------------------------------------------------------------------
__global__ void __launch_bounds__(256) ctx_mma()
{
    __shared__ uint32_t cs[4][2048];
    const int bh = blockIdx.x, b = bh >> 4, h = bh & 15;
    const int n0 = blockIdx.y << 10;
    const int tid = threadIdx.x, lane = tid & 31, wid = tid >> 5;
    const int wd = wid >> 1, we = wid & 1;
    const uint32_t sbase = smem_u32(cs);

    const uint32_t* KmP = g_KmB + (size_t)b * NN * DW + h * 32;
    const uint32_t* VbP = g_Vb  + (size_t)b * NN * DW + h * 32;

    const int lop = tid >> 7, t7 = tid & 127;
    const int lrow = t7 >> 2, lc2 = (t7 & 3) << 1;
    const uint32_t* lsrc = (lop ? VbP : KmP) + (size_t)(n0 + lrow) * DW;
    const uint32_t d0 = sbase + (((lop << 10) + lrow * 32 + ((lc2       ^ (lrow & 7)) << 2)) << 2);
    const uint32_t d1 = sbase + (((lop << 10) + lrow * 32 + (((lc2 + 1) ^ (lrow & 7)) << 2)) << 2);

    auto issue = [&](int t) {
        const uint32_t so = (uint32_t)(t & 3) << 13;
        const uint32_t* s = lsrc + (size_t)(t << 5) * DW;
        CP_ASYNC16(d0 + so, s + (lc2 << 2));
        CP_ASYNC16(d1 + so, s + ((lc2 + 1) << 2));
    };

    const int arow = (lane & 7) | ((lane & 16) >> 1);
    const int achk = (wd << 1) + ((lane >> 3) & 1);
    const int brow = lane & 15;

    float acc[4][4];
    #pragma unroll
    for (int i = 0; i < 4; i++)
        #pragma unroll
        for (int j = 0; j < 4; j++) acc[i][j] = 0.f;

    auto compute = [&](int stg) {
        const uint32_t so = (uint32_t)stg << 13;
        #pragma unroll
        for (int ks = 0; ks < 2; ks++) {
            uint32_t af[4], bg[2][4];
            {
                const int r = (ks << 4) + arow;
                LDM_X4T(af, sbase + so + ((r * 32 + ((achk ^ (r & 7)) << 2)) << 2));
            }
            #pragma unroll
            for (int np = 0; np < 2; np++) {
                const int r = (ks << 4) + brow;
                const int c = (we << 2) + (np << 1) + (lane >> 4);
                LDM_X4T(bg[np], sbase + so + ((1024 + r * 32 + ((c ^ (r & 7)) << 2)) << 2));
            }
            #pragma unroll
            for (int nf = 0; nf < 4; nf++)
                MMA_BF16(acc[nf], af,
                         bg[nf >> 1][(nf & 1) << 1], bg[nf >> 1][((nf & 1) << 1) + 1]);
        }
    };

    issue(0); CP_COMMIT();
    issue(1); CP_COMMIT();
    issue(2); CP_COMMIT();
    for (int t = 0; t < 32; t++) {
        CP_WAIT2();
        __syncthreads();
        compute(t & 3);
        if (t + 3 < 32) issue(t + 3);
        CP_COMMIT();
    }

    float* o = g_ctx + (((size_t)blockIdx.y * (BB * HH) + bh) << 12);
    const int d = (wd << 4) + (lane >> 2);
    #pragma unroll
    for (int nf = 0; nf < 4; nf++) {
        const int e = (we << 5) + (nf << 3) + ((lane & 3) << 1);
        *(float2*)(o + d * 64 + e)       = make_float2(acc[nf][0], acc[nf][1]);
        *(float2*)(o + (d + 8) * 64 + e) = make_float2(acc[nf][2], acc[nf][3]);
    }
}

// ---------------------------------------------------------------------------
// Mbig^T packed: g_Mtb[b][n][k/2] = pack(sum_e ctx[b,h][d][e]*Wo[h*64+e][n])
// ---------------------------------------------------------------------------
__global__ void __launch_bounds__(256) mbig_kernel(const float* __restrict__ Wo)
{
    const int bh = blockIdx.x, b = bh >> 4, h = bh & 15;
    const int c0 = blockIdx.y << 6;

    __shared__ float csx[64][64];
    __shared__ float ws[64][64];
    const int tid = threadIdx.x;

    for (int i = tid; i < 4096; i += 256) {
        float sum = 0.f;
        #pragma unroll
        for (int sp = 0; sp < CTXSP; sp++)
            sum += g_ctx[(((size_t)sp * (BB * HH) + bh) << 12) + i];
        csx[i >> 6][i & 63] = sum;
    }
    for (int i = tid; i < 1024; i += 256) {
        int rr = i >> 4, cc = (i & 15) << 2;
        *(float4*)&ws[rr][cc] =
            *(const float4*)(Wo + (size_t)(h * DH + rr) * DD + c0 + cc);
    }
    __syncthreads();

    const int r0 = (tid >> 4) << 2, cc0 = (tid & 15) << 2;
    float acc[4][4] = {};
    #pragma unroll 16
    for (int k = 0; k < 64; k++) {
        float a[4], w[4];
        #pragma unroll
        for (int i = 0; i < 4; i++) a[i] = csx[r0 + i][k];
        *(float4*)w = *(float4*)&ws[k][cc0];
        #pragma unroll
        for (int i = 0; i < 4; i++)
            #pragma unroll
            for (int j = 0; j < 4; j++)
                acc[i][j] = fmaf(a[i], w[j], acc[i][j]);
    }
    uint32_t* ob = g_Mtb + ((size_t)b * DD * DW);
    const int kb2 = (h * DH + r0) >> 1;
    #pragma unroll
    for (int j = 0; j < 4; j++) {
        const size_t n = (size_t)(c0 + cc0 + j);
        ob[n * DW + kb2]     = pack2(acc[0][j], acc[1][j]);
        ob[n * DW + kb2 + 1] = pack2(acc[2][j], acc[3][j]);
    }
}

// ---------------------------------------------------------------------------
// Launcher. Inputs: 0:x 1:Wq 2:bq 3:Wk(dead) 4:bk(dead) 5:Wv 6:bv 7:Wo 8:bo
// ---------------------------------------------------------------------------
extern "C" void kernel_launch(void* const* d_in, const int* in_sizes, int n_in,
                              void* d_out, int out_size)
{
    const float* x  = (const float*)d_in[0];
    const float* Wq = (const float*)d_in[1];
    const float* bq = (const float*)d_in[2];
    const float* Wv = (const float*)d_in[5];
    const float* bv = (const float*)d_in[6];
    const float* Wo = (const float*)d_in[7];
    const float* bo = (const float*)d_in[8];
    float* out = (float*)d_out;

    uint32_t *xb, *Qb, *Vb, *Wqvb, *Mtb;
    cudaGetSymbolAddress((void**)&xb,   g_xb);
    cudaGetSymbolAddress((void**)&Qb,   g_Qb);
    cudaGetSymbolAddress((void**)&Vb,   g_Vb);
    cudaGetSymbolAddress((void**)&Wqvb, g_Wqvb);
    cudaGetSymbolAddress((void**)&Mtb,  g_Mtb);

    cudaFuncSetAttribute((const void*)gemm_qv,
                         cudaFuncAttributeMaxDynamicSharedMemorySize, GEMM_SMEM);
    cudaFuncSetAttribute((const void*)gemm_out,
                         cudaFuncAttributeMaxDynamicSharedMemorySize, GEMM_SMEM);

    pack_rows<<<(BB * NN * DD) / (256 * 8), 256>>>(x, xb);
    pack_w<<<dim3(DD / 32, DD / 64), 256>>>(Wq, Wqvb);
    pack_w<<<dim3(DD / 32, DD / 64), 256>>>(Wv, Wqvb + (size_t)DD * DW);

    // Merged: Q = softmax(x@Wq + bq)*s -> Qb ; V = x@Wv + bv -> Vb
    gemm_qv<<<dim3(2 * DD / 128, NN / 128, BB), 256, GEMM_SMEM>>>(
        xb, Wqvb, bq, bv, Qb, Vb);

    // Km = softmax(Qb, seq) * s  (packed bf16; 2-pass, bounded values)
    col_softmax<<<dim3(DD / 32, BB), 512>>>();

    // ctx partials (tensor cores), then Mbig^T packed
    ctx_mma<<<dim3(BB * HH, CTXSP), 256>>>();
    mbig_kernel<<<dim3(BB * HH, DD / 64), 256>>>(Wo);

    // out[b] = Qs[b] @ Mbig[b] + bo
    gemm_out<<<dim3(DD / 128, NN / 128, BB), 256, GEMM_SMEM>>>(Qb, Mtb, bo, out);
}